// round 2
// baseline (speedup 1.0000x reference)
#include <cuda_runtime.h>
#include <math.h>

// Problem constants (fixed by the dataset)
#define MAXN 50000
#define MAXE 800000
#define D    128
#define BN_EPS 1e-5f

// ---------------- scratch (static __device__ — no allocations allowed) ----
__device__ float g_h0[MAXN * D];
__device__ float g_h1[MAXN * D];
__device__ float g_h2[MAXN * D];
__device__ float g_z [MAXN * D];
__device__ float g_norm[MAXN];
__device__ int   g_deg[MAXN];
__device__ int   g_rowptr[MAXN + 1];
__device__ int   g_cursor[MAXN];
__device__ int   g_csrsrc[MAXE];
__device__ float g_bnacc[512];    // [layer][sum|sumsq][128]
__device__ float g_colsum[128];

// ---------------- init: zero accumulators ---------------------------------
__global__ void init_kernel(int n) {
    int i = blockIdx.x * blockDim.x + threadIdx.x;
    if (i < n)   g_deg[i] = 0;
    if (i < 512) g_bnacc[i] = 0.f;
    if (i < 128) g_colsum[i] = 0.f;
}

// ---------------- degree histogram -----------------------------------------
__global__ void count_deg_kernel(const int* __restrict__ dst, int e) {
    int i = blockIdx.x * blockDim.x + threadIdx.x;
    if (i < e) atomicAdd(&g_deg[dst[i]], 1);
}

// ---------------- single-block exclusive scan + norm -----------------------
__global__ void scan_kernel(int n) {
    __shared__ int sm[2][1024];
    int t = threadIdx.x;
    int carry = 0;
    for (int base = 0; base < n; base += 1024) {
        int i = base + t;
        int v = (i < n) ? g_deg[i] : 0;
        if (i < n) g_norm[i] = rsqrtf((float)(v > 0 ? v : 1));
        sm[0][t] = v;
        __syncthreads();
        int cur = 0;
        #pragma unroll
        for (int off = 1; off < 1024; off <<= 1) {
            int val = sm[cur][t];
            if (t >= off) val += sm[cur][t - off];
            sm[cur ^ 1][t] = val;
            __syncthreads();
            cur ^= 1;
        }
        int incl = sm[cur][t];
        int tot  = sm[cur][1023];
        if (i < n) {
            int ex = carry + incl - v;
            g_rowptr[i] = ex;
            g_cursor[i] = ex;
        }
        __syncthreads();   // protect sm before next chunk overwrites
        carry += tot;
    }
    if (t == 0) g_rowptr[n] = carry;
}

// ---------------- CSR scatter (counting sort by dst) -----------------------
__global__ void scatter_kernel(const int* __restrict__ src,
                               const int* __restrict__ dst, int e) {
    int i = blockIdx.x * blockDim.x + threadIdx.x;
    if (i < e) {
        int d = dst[i];
        int p = atomicAdd(&g_cursor[d], 1);
        g_csrsrc[p] = src[i];
    }
}

// ---------------- SpMM: hout[v] = norm[v] * sum_{e in CSR[v]} norm[s]*hin[s]
__global__ void spmm_kernel(const float* __restrict__ hin,
                            float* __restrict__ hout) {
    int v = blockIdx.x;
    int t = threadIdx.x;             // channel 0..127
    int beg = g_rowptr[v], end = g_rowptr[v + 1];
    __shared__ int   sidx[128];
    __shared__ float snrm[128];
    float acc = 0.f;
    for (int chunk = beg; chunk < end; chunk += 128) {
        int n = min(128, end - chunk);
        if (t < n) {
            int s = g_csrsrc[chunk + t];
            sidx[t] = s * D;
            snrm[t] = g_norm[s];
        }
        __syncthreads();
        #pragma unroll 4
        for (int j = 0; j < n; j++)
            acc += __ldg(&hin[sidx[j] + t]) * snrm[j];
        __syncthreads();
    }
    hout[v * D + t] = acc * g_norm[v];
}

// ---------------- tiled fp32 GEMM: C = act([A0|A1|A2] @ W + bias) ----------
// BM=128, BN=128 (full D), BK=16; 256 threads, 8x8 micro-tile per thread.
// Each 8-consecutive-kt group reads from one of the three A segments.
#define BM 128
#define BK 16
__global__ __launch_bounds__(256, 2)
void gemm_kernel(const float* __restrict__ A0, const float* __restrict__ A1,
                 const float* __restrict__ A2, const float* __restrict__ W,
                 const float* __restrict__ bias, float* __restrict__ C,
                 int nrows, int ktiles, int act) {
    __shared__ float As[BK][136];   // pitch 136: float4-aligned, conflict-free transpose
    __shared__ float Ws[BK][128];

    int tid = threadIdx.x;
    int tx = tid & 15;              // col group
    int ty = tid >> 4;              // row group
    int r0 = blockIdx.x * BM;

    float acc[8][8];
    #pragma unroll
    for (int i = 0; i < 8; i++)
        #pragma unroll
        for (int j = 0; j < 8; j++) acc[i][j] = 0.f;

    for (int kt = 0; kt < ktiles; kt++) {
        int seg = kt >> 3;
        const float* Ap = (seg == 0) ? A0 : ((seg == 1) ? A1 : A2);
        int kk = (kt & 7) * BK;

        // load A tile [128 rows x 16 cols], transposed into As[k][row]
        #pragma unroll
        for (int it = 0; it < 2; it++) {
            int q   = tid + it * 256;
            int row = q >> 2;
            int c4  = (q & 3) * 4;
            int gr  = r0 + row;
            float4 v = make_float4(0.f, 0.f, 0.f, 0.f);
            if (gr < nrows)
                v = *(const float4*)&Ap[gr * D + kk + c4];
            As[c4 + 0][row] = v.x;
            As[c4 + 1][row] = v.y;
            As[c4 + 2][row] = v.z;
            As[c4 + 3][row] = v.w;
        }
        // load W tile [16 x 128]
        #pragma unroll
        for (int it = 0; it < 2; it++) {
            int q    = tid + it * 256;
            int krow = q >> 5;
            int c4   = (q & 31) * 4;
            *(float4*)&Ws[krow][c4] =
                *(const float4*)&W[(kt * BK + krow) * 128 + c4];
        }
        __syncthreads();

        #pragma unroll
        for (int k = 0; k < BK; k++) {
            float4 a0 = *(float4*)&As[k][ty * 8];
            float4 a1 = *(float4*)&As[k][ty * 8 + 4];
            float4 b0 = *(float4*)&Ws[k][tx * 8];
            float4 b1 = *(float4*)&Ws[k][tx * 8 + 4];
            float a[8] = {a0.x, a0.y, a0.z, a0.w, a1.x, a1.y, a1.z, a1.w};
            float b[8] = {b0.x, b0.y, b0.z, b0.w, b1.x, b1.y, b1.z, b1.w};
            #pragma unroll
            for (int i = 0; i < 8; i++)
                #pragma unroll
                for (int j = 0; j < 8; j++)
                    acc[i][j] = fmaf(a[i], b[j], acc[i][j]);
        }
        __syncthreads();
    }

    // epilogue
    #pragma unroll
    for (int i = 0; i < 8; i++) {
        int gr = r0 + ty * 8 + i;
        if (gr >= nrows) continue;
        float o[8];
        #pragma unroll
        for (int j = 0; j < 8; j++) {
            float v = acc[i][j];
            if (bias) v += bias[tx * 8 + j];
            if (act == 1) v = 1.f / (1.f + expf(-v));
            o[j] = v;
        }
        *(float4*)&C[gr * D + tx * 8]     = make_float4(o[0], o[1], o[2], o[3]);
        *(float4*)&C[gr * D + tx * 8 + 4] = make_float4(o[4], o[5], o[6], o[7]);
    }
}

// ---------------- BN stats: per-channel sum & sumsq ------------------------
__global__ void bn_stats_kernel(const float* __restrict__ z,
                                float* __restrict__ acc, int n) {
    int c  = threadIdx.x;           // channel
    int r0 = blockIdx.x * 256;
    int r1 = min(r0 + 256, n);
    float s = 0.f, ss = 0.f;
    for (int r = r0; r < r1; r++) {
        float v = z[r * D + c];
        s += v;
        ss += v * v;
    }
    atomicAdd(&acc[c],       s);
    atomicAdd(&acc[128 + c], ss);
}

// ---------------- BN apply + ReLU (optionally accumulate column sums) ------
__global__ void bn_apply_kernel(const float* __restrict__ z,
                                float* __restrict__ hout,
                                const float* __restrict__ acc,
                                const float* __restrict__ gamma,
                                const float* __restrict__ beta,
                                int n, int docol) {
    int c  = threadIdx.x;
    float mu  = acc[c] / (float)n;
    float var = acc[128 + c] / (float)n - mu * mu;
    float scale = rsqrtf(var + BN_EPS) * gamma[c];
    float shift = beta[c] - mu * scale;
    int r0 = blockIdx.x * 256;
    int r1 = min(r0 + 256, n);
    float cs = 0.f;
    for (int r = r0; r < r1; r++) {
        float v = z[r * D + c] * scale + shift;
        v = fmaxf(v, 0.f);
        hout[r * D + c] = v;
        cs += v;
    }
    if (docol) atomicAdd(&g_colsum[c], cs);
}

// ---------------- final: out = colmean(h) @ Wd + bd ------------------------
__global__ void final_kernel(const float* __restrict__ Wd,
                             const float* __restrict__ bd,
                             float* __restrict__ out, int n) {
    int j = threadIdx.x;            // 0..255
    float inv_n = 1.f / (float)n;
    float acc = bd[j];
    #pragma unroll 4
    for (int c = 0; c < D; c++)
        acc = fmaf(__ldg(&g_colsum[c]) * inv_n, Wd[c * 256 + j], acc);
    out[j] = acc;
}

// ---------------- launch ----------------------------------------------------
extern "C" void kernel_launch(void* const* d_in, const int* in_sizes, int n_in,
                              void* d_out, int out_size) {
    const float* features = (const float*)d_in[0];
    const int*   src      = (const int*)  d_in[1];
    const int*   dst      = (const int*)  d_in[2];
    const float* Wg  = (const float*)d_in[3];
    const float* bg  = (const float*)d_in[4];
    const float* Wc1 = (const float*)d_in[5];
    const float* g1  = (const float*)d_in[6];
    const float* b1  = (const float*)d_in[7];
    const float* Wc2 = (const float*)d_in[8];
    const float* g2  = (const float*)d_in[9];
    const float* b2  = (const float*)d_in[10];
    const float* Wd  = (const float*)d_in[11];
    const float* bd  = (const float*)d_in[12];
    float* out = (float*)d_out;

    int N = in_sizes[0] / D;
    int E = in_sizes[1];

    void* p;
    float *h0, *h1, *h2, *z, *bnacc;
    cudaGetSymbolAddress(&p, g_h0);    h0 = (float*)p;
    cudaGetSymbolAddress(&p, g_h1);    h1 = (float*)p;
    cudaGetSymbolAddress(&p, g_h2);    h2 = (float*)p;
    cudaGetSymbolAddress(&p, g_z);     z  = (float*)p;
    cudaGetSymbolAddress(&p, g_bnacc); bnacc = (float*)p;

    int gb  = (N + BM - 1) / BM;        // GEMM row blocks
    int bnb = (N + 255) / 256;          // BN blocks

    // graph structure: degrees -> norm -> CSR by dst
    init_kernel<<<(N + 255) / 256, 256>>>(N);
    count_deg_kernel<<<(E + 255) / 256, 256>>>(dst, E);
    scan_kernel<<<1, 1024>>>(N);
    scatter_kernel<<<(E + 255) / 256, 256>>>(src, dst, E);

    // node gating: h0 = sigmoid(X @ Wg + bg)
    gemm_kernel<<<gb, 256>>>(features, nullptr, nullptr, Wg, bg, h0, N, 8, 1);

    // ---- layer 1 ----
    spmm_kernel<<<N, 128>>>(h0, h1);
    spmm_kernel<<<N, 128>>>(h1, h2);
    gemm_kernel<<<gb, 256>>>(h0, h1, h2, Wc1, nullptr, z, N, 24, 0);
    bn_stats_kernel<<<bnb, 128>>>(z, bnacc, N);
    bn_apply_kernel<<<bnb, 128>>>(z, h0, bnacc, g1, b1, N, 0);

    // ---- layer 2 ----
    spmm_kernel<<<N, 128>>>(h0, h1);
    spmm_kernel<<<N, 128>>>(h1, h2);
    gemm_kernel<<<gb, 256>>>(h0, h1, h2, Wc2, nullptr, z, N, 24, 0);
    bn_stats_kernel<<<bnb, 128>>>(z, bnacc + 256, N);
    bn_apply_kernel<<<bnb, 128>>>(z, h0, bnacc + 256, g2, b2, N, 1);

    // readout: mean(h @ Wd + bd) == colmean(h) @ Wd + bd
    final_kernel<<<1, 256>>>(Wd, bd, out, N);
}

// round 3
// speedup vs baseline: 2.1978x; 2.1978x over previous
#include <cuda_runtime.h>
#include <cuda_bf16.h>
#include <math.h>

#define MAXN 50000
#define MAXE 800000
#define D    128
#define BN_EPS 1e-5f

// ---------------- scratch (static __device__ — no allocations) -------------
__device__ __align__(16) __nv_bfloat16 g_featb[MAXN * D];
__device__ __align__(16) __nv_bfloat16 g_hb0[MAXN * D];
__device__ __align__(16) __nv_bfloat16 g_hb1[MAXN * D];
__device__ __align__(16) __nv_bfloat16 g_hb2[MAXN * D];
__device__ __align__(16) __nv_bfloat16 g_wb[114688];     // Wg|Wc1|Wc2 bf16
__device__ __align__(16) float g_z[MAXN * D];
__device__ float g_norm[MAXN];
__device__ int   g_deg[MAXN];
__device__ int   g_rowptr[MAXN + 1];
__device__ int   g_cursor[MAXN];
__device__ int   g_csrsrc[MAXE];
__device__ int   g_blocksum[64];
__device__ float g_bnacc[512];
__device__ float g_colsum[128];

// ---------------- init ------------------------------------------------------
__global__ void init_kernel(int n) {
    int i = blockIdx.x * blockDim.x + threadIdx.x;
    if (i < n)   g_deg[i] = 0;
    if (i < 512) g_bnacc[i] = 0.f;
    if (i < 128) g_colsum[i] = 0.f;
}

__global__ void count_deg_kernel(const int* __restrict__ dst, int e) {
    int i = blockIdx.x * blockDim.x + threadIdx.x;
    if (i < e) atomicAdd(&g_deg[dst[i]], 1);
}

// ---------------- 3-phase parallel scan -------------------------------------
__global__ void scanA_kernel(int n) {
    __shared__ int sm[1024];
    int t = threadIdx.x;
    int i = blockIdx.x * 1024 + t;
    int v = (i < n) ? g_deg[i] : 0;
    if (i < n) g_norm[i] = rsqrtf((float)(v > 0 ? v : 1));
    sm[t] = v;
    __syncthreads();
    #pragma unroll
    for (int off = 1; off < 1024; off <<= 1) {
        int x = sm[t];
        if (t >= off) x += sm[t - off];
        __syncthreads();
        sm[t] = x;
        __syncthreads();
    }
    if (i < n) g_rowptr[i] = sm[t] - v;        // local exclusive
    if (t == 1023) g_blocksum[blockIdx.x] = sm[t];
}

__global__ void scanB_kernel(int nb) {
    __shared__ int sm[64];
    int t = threadIdx.x;
    int v = (t < nb) ? g_blocksum[t] : 0;
    sm[t] = v;
    __syncthreads();
    #pragma unroll
    for (int off = 1; off < 64; off <<= 1) {
        int x = sm[t];
        if (t >= off) x += sm[t - off];
        __syncthreads();
        sm[t] = x;
        __syncthreads();
    }
    if (t < nb) g_blocksum[t] = sm[t] - v;     // exclusive block offsets
}

__global__ void scanC_kernel(int n, int e) {
    int i = blockIdx.x * blockDim.x + threadIdx.x;
    if (i < n) {
        int r = g_rowptr[i] + g_blocksum[i >> 10];
        g_rowptr[i] = r;
        g_cursor[i] = r;
    }
    if (i == 0) g_rowptr[n] = e;
}

__global__ void scatter_kernel(const int* __restrict__ src,
                               const int* __restrict__ dst, int e) {
    int i = blockIdx.x * blockDim.x + threadIdx.x;
    if (i < e) {
        int d = dst[i];
        int p = atomicAdd(&g_cursor[d], 1);
        g_csrsrc[p] = src[i];
    }
}

// ---------------- fp32 -> bf16 conversions ----------------------------------
__global__ void cvt_feat_kernel(const float* __restrict__ x, int n) {
    int i = blockIdx.x * blockDim.x + threadIdx.x;
    if (i < n) g_featb[i] = __float2bfloat16(x[i]);
}

__global__ void cvt_w_kernel(const float* __restrict__ Wg,
                             const float* __restrict__ Wc1,
                             const float* __restrict__ Wc2) {
    int i = blockIdx.x * blockDim.x + threadIdx.x;
    if (i < 16384)       g_wb[i] = __float2bfloat16(Wg[i]);
    else if (i < 65536)  g_wb[i] = __float2bfloat16(Wc1[i - 16384]);
    else if (i < 114688) g_wb[i] = __float2bfloat16(Wc2[i - 65536]);
}

// ---------------- warp-per-node SpMM (bf16 in/out, fp32 accum) --------------
// hout[v] = norm[v] * sum_{s in CSR[v]} norm[s] * hin[s]
__global__ void spmm_kernel(const unsigned int* __restrict__ hin,
                            unsigned int* __restrict__ hout, int n) {
    int node = blockIdx.x * 8 + (threadIdx.x >> 5);
    int lane = threadIdx.x & 31;
    if (node >= n) return;
    int beg = g_rowptr[node], end = g_rowptr[node + 1];
    float2 acc0 = make_float2(0.f, 0.f);
    float2 acc1 = make_float2(0.f, 0.f);
    for (int chunk = beg; chunk < end; chunk += 32) {
        int cnt = min(32, end - chunk);
        int s = 0; float nm = 0.f;
        if (lane < cnt) {
            s = g_csrsrc[chunk + lane];
            nm = g_norm[s];
        }
        #pragma unroll 4
        for (int j = 0; j < cnt; j++) {
            int  si = __shfl_sync(0xffffffffu, s, j);
            float w = __shfl_sync(0xffffffffu, nm, j);
            unsigned int p0 = __ldg(&hin[si * 64 + lane]);
            unsigned int p1 = __ldg(&hin[si * 64 + 32 + lane]);
            float2 f0 = __bfloat1622float2(*(__nv_bfloat162*)&p0);
            float2 f1 = __bfloat1622float2(*(__nv_bfloat162*)&p1);
            acc0.x = fmaf(f0.x, w, acc0.x);
            acc0.y = fmaf(f0.y, w, acc0.y);
            acc1.x = fmaf(f1.x, w, acc1.x);
            acc1.y = fmaf(f1.y, w, acc1.y);
        }
    }
    float nv = g_norm[node];
    __nv_bfloat162 o0 = __float22bfloat162_rn(make_float2(acc0.x * nv, acc0.y * nv));
    __nv_bfloat162 o1 = __float22bfloat162_rn(make_float2(acc1.x * nv, acc1.y * nv));
    hout[node * 64 + lane]      = *(unsigned int*)&o0;
    hout[node * 64 + 32 + lane] = *(unsigned int*)&o1;
}

// ---------------- tensor-core GEMM helpers ----------------------------------
__device__ __forceinline__ void ldsm4(unsigned (&r)[4], unsigned addr) {
    asm volatile("ldmatrix.sync.aligned.m8n8.x4.shared.b16 {%0,%1,%2,%3}, [%4];"
        : "=r"(r[0]), "=r"(r[1]), "=r"(r[2]), "=r"(r[3]) : "r"(addr));
}
__device__ __forceinline__ void ldsm4t(unsigned (&r)[4], unsigned addr) {
    asm volatile("ldmatrix.sync.aligned.m8n8.x4.trans.shared.b16 {%0,%1,%2,%3}, [%4];"
        : "=r"(r[0]), "=r"(r[1]), "=r"(r[2]), "=r"(r[3]) : "r"(addr));
}
__device__ __forceinline__ void mma_bf16(float (&c)[4], const unsigned (&a)[4],
                                         unsigned b0, unsigned b1) {
    asm volatile("mma.sync.aligned.m16n8k16.row.col.f32.bf16.bf16.f32 "
        "{%0,%1,%2,%3}, {%4,%5,%6,%7}, {%8,%9}, {%0,%1,%2,%3};"
        : "+f"(c[0]), "+f"(c[1]), "+f"(c[2]), "+f"(c[3])
        : "r"(a[0]), "r"(a[1]), "r"(a[2]), "r"(a[3]), "r"(b0), "r"(b1));
}

// C = act([A0|A1|A2] @ Wb) — A segs bf16 [nrows,128], Wb bf16 [ktiles*32,128].
// act=0: write fp32 to outf.  act=1: +bias, sigmoid, write bf16 to outb.
#define A_STRIDE 56      // bf16 elems per A smem row (112B: conflict-free ldmatrix)
#define B_STRIDE 136     // bf16 elems per B smem row (272B: conflict-free ldmatrix.trans)
__global__ __launch_bounds__(256, 2)
void gemm_bf16_kernel(const __nv_bfloat16* __restrict__ A0,
                      const __nv_bfloat16* __restrict__ A1,
                      const __nv_bfloat16* __restrict__ A2,
                      const __nv_bfloat16* __restrict__ Wb,
                      const float* __restrict__ bias,
                      float* __restrict__ outf,
                      unsigned int* __restrict__ outb,
                      int nrows, int ktiles, int act) {
    __shared__ __align__(16) unsigned short As[128 * A_STRIDE];
    __shared__ __align__(16) unsigned short Bs[32 * B_STRIDE];

    int tid  = threadIdx.x;
    int lane = tid & 31;
    int wid  = tid >> 5;
    int m_warp = (wid >> 1) * 32;     // 0,32,64,96
    int n_warp = (wid & 1) * 64;      // 0,64
    int r0 = blockIdx.x * 128;

    unsigned as_base = (unsigned)__cvta_generic_to_shared(As);
    unsigned bs_base = (unsigned)__cvta_generic_to_shared(Bs);

    float acc[2][8][4];
    #pragma unroll
    for (int mt = 0; mt < 2; mt++)
        #pragma unroll
        for (int nt = 0; nt < 8; nt++)
            #pragma unroll
            for (int k = 0; k < 4; k++) acc[mt][nt][k] = 0.f;

    for (int kt = 0; kt < ktiles; kt++) {
        int seg = kt >> 2;
        const __nv_bfloat16* Ap = (seg == 0) ? A0 : ((seg == 1) ? A1 : A2);
        int kk = (kt & 3) * 32;

        // load A tile [128 x 32] bf16
        #pragma unroll
        for (int it = 0; it < 2; it++) {
            int idx = tid + it * 256;            // 0..511
            int row = idx >> 2;
            int ch  = idx & 3;
            int gr  = r0 + row;
            uint4 v = make_uint4(0u, 0u, 0u, 0u);
            if (gr < nrows)
                v = *(const uint4*)(Ap + gr * 128 + kk + ch * 8);
            *(uint4*)(As + row * A_STRIDE + ch * 8) = v;
        }
        // load B tile [32 x 128] bf16
        #pragma unroll
        for (int it = 0; it < 2; it++) {
            int idx = tid + it * 256;
            int row = idx >> 4;
            int ch  = idx & 15;
            uint4 v = *(const uint4*)(Wb + (kt * 32 + row) * 128 + ch * 8);
            *(uint4*)(Bs + row * B_STRIDE + ch * 8) = v;
        }
        __syncthreads();

        #pragma unroll
        for (int ksub = 0; ksub < 2; ksub++) {
            unsigned a[2][4];
            #pragma unroll
            for (int mt = 0; mt < 2; mt++) {
                unsigned addr = as_base +
                    ((m_warp + mt * 16 + (lane & 15)) * A_STRIDE +
                     ksub * 16 + (lane >> 4) * 8) * 2;
                ldsm4(a[mt], addr);
            }
            unsigned b[4][4];
            #pragma unroll
            for (int nt2 = 0; nt2 < 4; nt2++) {
                unsigned addr = bs_base +
                    ((ksub * 16 + (lane & 15)) * B_STRIDE +
                     n_warp + nt2 * 16 + (lane >> 4) * 8) * 2;
                ldsm4t(b[nt2], addr);
            }
            #pragma unroll
            for (int mt = 0; mt < 2; mt++)
                #pragma unroll
                for (int nt = 0; nt < 8; nt++)
                    mma_bf16(acc[mt][nt], a[mt],
                             b[nt >> 1][(nt & 1) * 2],
                             b[nt >> 1][(nt & 1) * 2 + 1]);
        }
        __syncthreads();
    }

    // epilogue
    int g  = lane >> 2;
    int t4 = lane & 3;
    #pragma unroll
    for (int mt = 0; mt < 2; mt++) {
        int row0 = r0 + m_warp + mt * 16 + g;
        #pragma unroll
        for (int nt = 0; nt < 8; nt++) {
            int col = n_warp + nt * 8 + 2 * t4;
            float c0 = acc[mt][nt][0], c1 = acc[mt][nt][1];
            float c2 = acc[mt][nt][2], c3 = acc[mt][nt][3];
            if (act == 0) {
                if (row0 < nrows)
                    *(float2*)&outf[row0 * 128 + col] = make_float2(c0, c1);
                if (row0 + 8 < nrows)
                    *(float2*)&outf[(row0 + 8) * 128 + col] = make_float2(c2, c3);
            } else {
                float b0 = bias[col], b1 = bias[col + 1];
                c0 = 1.f / (1.f + __expf(-(c0 + b0)));
                c1 = 1.f / (1.f + __expf(-(c1 + b1)));
                c2 = 1.f / (1.f + __expf(-(c2 + b0)));
                c3 = 1.f / (1.f + __expf(-(c3 + b1)));
                if (row0 < nrows) {
                    __nv_bfloat162 p = __float22bfloat162_rn(make_float2(c0, c1));
                    outb[row0 * 64 + (col >> 1)] = *(unsigned int*)&p;
                }
                if (row0 + 8 < nrows) {
                    __nv_bfloat162 p = __float22bfloat162_rn(make_float2(c2, c3));
                    outb[(row0 + 8) * 64 + (col >> 1)] = *(unsigned int*)&p;
                }
            }
        }
    }
}

// ---------------- BN stats / apply ------------------------------------------
__global__ void bn_stats_kernel(const float* __restrict__ z,
                                float* __restrict__ acc, int n) {
    int c  = threadIdx.x;
    int r0 = blockIdx.x * 256;
    int r1 = min(r0 + 256, n);
    float s = 0.f, ss = 0.f;
    for (int r = r0; r < r1; r++) {
        float v = z[r * D + c];
        s += v;
        ss = fmaf(v, v, ss);
    }
    atomicAdd(&acc[c],       s);
    atomicAdd(&acc[128 + c], ss);
}

__global__ void bn_apply_kernel(const float* __restrict__ z,
                                __nv_bfloat16* __restrict__ hout,
                                const float* __restrict__ acc,
                                const float* __restrict__ gamma,
                                const float* __restrict__ beta,
                                int n, int docol) {
    int c  = threadIdx.x;
    float mu  = acc[c] / (float)n;
    float var = acc[128 + c] / (float)n - mu * mu;
    float scale = rsqrtf(var + BN_EPS) * gamma[c];
    float shift = beta[c] - mu * scale;
    int r0 = blockIdx.x * 256;
    int r1 = min(r0 + 256, n);
    float cs = 0.f;
    for (int r = r0; r < r1; r++) {
        float v = fmaf(z[r * D + c], scale, shift);
        v = fmaxf(v, 0.f);
        hout[r * D + c] = __float2bfloat16(v);
        cs += v;
    }
    if (docol) atomicAdd(&g_colsum[c], cs);
}

// ---------------- readout: out = colmean(h) @ Wd + bd -----------------------
__global__ void final_kernel(const float* __restrict__ Wd,
                             const float* __restrict__ bd,
                             float* __restrict__ out, int n) {
    int j = threadIdx.x;
    float inv_n = 1.f / (float)n;
    float acc = bd[j];
    #pragma unroll 4
    for (int c = 0; c < D; c++)
        acc = fmaf(__ldg(&g_colsum[c]) * inv_n, Wd[c * 256 + j], acc);
    out[j] = acc;
}

// ---------------- launch ----------------------------------------------------
extern "C" void kernel_launch(void* const* d_in, const int* in_sizes, int n_in,
                              void* d_out, int out_size) {
    const float* features = (const float*)d_in[0];
    const int*   src      = (const int*)  d_in[1];
    const int*   dst      = (const int*)  d_in[2];
    const float* Wg  = (const float*)d_in[3];
    const float* bg  = (const float*)d_in[4];
    const float* Wc1 = (const float*)d_in[5];
    const float* g1  = (const float*)d_in[6];
    const float* b1  = (const float*)d_in[7];
    const float* Wc2 = (const float*)d_in[8];
    const float* g2  = (const float*)d_in[9];
    const float* b2  = (const float*)d_in[10];
    const float* Wd  = (const float*)d_in[11];
    const float* bd  = (const float*)d_in[12];
    float* out = (float*)d_out;

    int N = in_sizes[0] / D;
    int E = in_sizes[1];

    void* p;
    __nv_bfloat16 *featb, *hb0, *hb1, *hb2, *wb;
    float *z, *bnacc;
    cudaGetSymbolAddress(&p, g_featb); featb = (__nv_bfloat16*)p;
    cudaGetSymbolAddress(&p, g_hb0);   hb0 = (__nv_bfloat16*)p;
    cudaGetSymbolAddress(&p, g_hb1);   hb1 = (__nv_bfloat16*)p;
    cudaGetSymbolAddress(&p, g_hb2);   hb2 = (__nv_bfloat16*)p;
    cudaGetSymbolAddress(&p, g_wb);    wb  = (__nv_bfloat16*)p;
    cudaGetSymbolAddress(&p, g_z);     z   = (float*)p;
    cudaGetSymbolAddress(&p, g_bnacc); bnacc = (float*)p;

    int gb   = (N + 127) / 128;
    int bnb  = (N + 255) / 256;
    int spb  = (N + 7) / 8;
    int nsb  = (N + 1023) / 1024;

    // graph structure
    init_kernel<<<(N + 255) / 256, 256>>>(N);
    count_deg_kernel<<<(E + 255) / 256, 256>>>(dst, E);
    scanA_kernel<<<nsb, 1024>>>(N);
    scanB_kernel<<<1, 64>>>(nsb);
    scanC_kernel<<<(N + 255) / 256, 256>>>(N, E);
    scatter_kernel<<<(E + 255) / 256, 256>>>(src, dst, E);

    // conversions
    cvt_feat_kernel<<<(N * D + 255) / 256, 256>>>(features, N * D);
    cvt_w_kernel<<<(114688 + 255) / 256, 256>>>(Wg, Wc1, Wc2);

    // gating: hb0 = sigmoid(featb @ Wg + bg)   (bf16 out)
    gemm_bf16_kernel<<<gb, 256>>>(featb, nullptr, nullptr, wb, bg,
                                  nullptr, (unsigned int*)hb0, N, 4, 1);

    // ---- layer 1 ----
    spmm_kernel<<<spb, 256>>>((const unsigned int*)hb0, (unsigned int*)hb1, N);
    spmm_kernel<<<spb, 256>>>((const unsigned int*)hb1, (unsigned int*)hb2, N);
    gemm_bf16_kernel<<<gb, 256>>>(hb0, hb1, hb2, wb + 16384, nullptr,
                                  z, nullptr, N, 12, 0);
    bn_stats_kernel<<<bnb, 128>>>(z, bnacc, N);
    bn_apply_kernel<<<bnb, 128>>>(z, hb0, bnacc, g1, b1, N, 0);

    // ---- layer 2 ----
    spmm_kernel<<<spb, 256>>>((const unsigned int*)hb0, (unsigned int*)hb1, N);
    spmm_kernel<<<spb, 256>>>((const unsigned int*)hb1, (unsigned int*)hb2, N);
    gemm_bf16_kernel<<<gb, 256>>>(hb0, hb1, hb2, wb + 65536, nullptr,
                                  z, nullptr, N, 12, 0);
    bn_stats_kernel<<<bnb, 128>>>(z, bnacc + 256, N);
    bn_apply_kernel<<<bnb, 128>>>(z, hb0, bnacc + 256, g2, b2, N, 1);

    // readout
    final_kernel<<<1, 256>>>(Wd, bd, out, N);
}

// round 4
// speedup vs baseline: 2.3713x; 1.0790x over previous
#include <cuda_runtime.h>
#include <cuda_bf16.h>
#include <math.h>

#define MAXN 50000
#define MAXE 800000
#define D    128
#define BN_EPS 1e-5f

// ---------------- scratch (static __device__ — no allocations) -------------
__device__ __align__(16) __nv_bfloat16 g_hb0[MAXN * D];
__device__ __align__(16) __nv_bfloat16 g_hb1[MAXN * D];
__device__ __align__(16) __nv_bfloat16 g_hb2[MAXN * D];
__device__ __align__(16) __nv_bfloat16 g_wb[114688];     // Wg|Wc1|Wc2 bf16
__device__ __align__(16) unsigned int g_zb[MAXN * 64];   // z as bf16x2 pairs
__device__ float g_norm[MAXN];
__device__ int   g_deg[MAXN];
__device__ int   g_rowptr[MAXN + 1];
__device__ int   g_cursor[MAXN];
__device__ int   g_csrsrc[MAXE];
__device__ int   g_blocksum[64];
__device__ float g_bnacc[512];
__device__ float g_colsum[128];

// ---------------- init: zero accumulators + convert weights ----------------
__global__ void init_kernel(int n, const float* __restrict__ Wg,
                            const float* __restrict__ Wc1,
                            const float* __restrict__ Wc2) {
    int i = blockIdx.x * blockDim.x + threadIdx.x;
    if (i < n)   g_deg[i] = 0;
    if (i < 512) g_bnacc[i] = 0.f;
    if (i < 128) g_colsum[i] = 0.f;
    if (i < 16384)       g_wb[i] = __float2bfloat16(Wg[i]);
    else if (i < 65536)  g_wb[i] = __float2bfloat16(Wc1[i - 16384]);
    else if (i < 114688) g_wb[i] = __float2bfloat16(Wc2[i - 65536]);
}

// ---------------- degree histogram (2 edges/thread) -------------------------
__global__ void count_deg_kernel(const int* __restrict__ dst, int e) {
    int i = blockIdx.x * blockDim.x + threadIdx.x;
    int half = e >> 1;
    if (i < half) {
        int2 d = ((const int2*)dst)[i];
        atomicAdd(&g_deg[d.x], 1);
        atomicAdd(&g_deg[d.y], 1);
    }
    if (i == 0 && (e & 1)) atomicAdd(&g_deg[dst[e - 1]], 1);
}

// ---------------- scan phase A: per-1024-chunk local scan -------------------
__global__ void scanA_kernel(int n) {
    __shared__ int sm[1024];
    int t = threadIdx.x;
    int i = blockIdx.x * 1024 + t;
    int v = (i < n) ? g_deg[i] : 0;
    if (i < n) g_norm[i] = rsqrtf((float)(v > 0 ? v : 1));
    sm[t] = v;
    __syncthreads();
    #pragma unroll
    for (int off = 1; off < 1024; off <<= 1) {
        int x = sm[t];
        if (t >= off) x += sm[t - off];
        __syncthreads();
        sm[t] = x;
        __syncthreads();
    }
    if (i < n) g_rowptr[i] = sm[t] - v;
    if (t == 1023) g_blocksum[blockIdx.x] = sm[t];
}

// ---------------- scan phase C: inline block-offset prefix + add ------------
__global__ void scanC_kernel(int n, int e, int nb) {
    __shared__ int pref[64];
    int t = threadIdx.x;
    if (t < 64) {
        int s = 0;
        for (int j = 0; j < t && j < nb; j++) s += g_blocksum[j];
        pref[t] = s;
    }
    __syncthreads();
    int i = blockIdx.x * blockDim.x + t;
    if (i < n) {
        int r = g_rowptr[i] + pref[i >> 10];
        g_rowptr[i] = r;
        g_cursor[i] = r;
    }
    if (i == 0) g_rowptr[n] = e;
}

// ---------------- CSR scatter (2 edges/thread) ------------------------------
__global__ void scatter_kernel(const int* __restrict__ src,
                               const int* __restrict__ dst, int e) {
    int i = blockIdx.x * blockDim.x + threadIdx.x;
    int half = e >> 1;
    if (i < half) {
        int2 d = ((const int2*)dst)[i];
        int2 s = ((const int2*)src)[i];
        int p0 = atomicAdd(&g_cursor[d.x], 1);
        g_csrsrc[p0] = s.x;
        int p1 = atomicAdd(&g_cursor[d.y], 1);
        g_csrsrc[p1] = s.y;
    }
    if (i == 0 && (e & 1)) {
        int p = atomicAdd(&g_cursor[dst[e - 1]], 1);
        g_csrsrc[p] = src[e - 1];
    }
}

// ---------------- warp-per-node SpMM (bf16 in/out, fp32 accum) --------------
__global__ void spmm_kernel(const uint2* __restrict__ hin,
                            uint2* __restrict__ hout, int n) {
    int node = blockIdx.x * 8 + (threadIdx.x >> 5);
    int lane = threadIdx.x & 31;
    if (node >= n) return;
    int beg = g_rowptr[node], end = g_rowptr[node + 1];
    float4 acc = make_float4(0.f, 0.f, 0.f, 0.f);
    for (int chunk = beg; chunk < end; chunk += 32) {
        int cnt = min(32, end - chunk);
        int s = 0; float nm = 0.f;
        if (lane < cnt) {
            s = g_csrsrc[chunk + lane];
            nm = g_norm[s];
        }
        #pragma unroll 4
        for (int j = 0; j < cnt; j++) {
            int  si = __shfl_sync(0xffffffffu, s, j);
            float w = __shfl_sync(0xffffffffu, nm, j);
            uint2 p = __ldg(&hin[si * 32 + lane]);
            float2 f0 = __bfloat1622float2(*(__nv_bfloat162*)&p.x);
            float2 f1 = __bfloat1622float2(*(__nv_bfloat162*)&p.y);
            acc.x = fmaf(f0.x, w, acc.x);
            acc.y = fmaf(f0.y, w, acc.y);
            acc.z = fmaf(f1.x, w, acc.z);
            acc.w = fmaf(f1.y, w, acc.w);
        }
    }
    float nv = g_norm[node];
    __nv_bfloat162 o0 = __float22bfloat162_rn(make_float2(acc.x * nv, acc.y * nv));
    __nv_bfloat162 o1 = __float22bfloat162_rn(make_float2(acc.z * nv, acc.w * nv));
    hout[node * 32 + lane] = make_uint2(*(unsigned*)&o0, *(unsigned*)&o1);
}

// ---------------- tensor-core GEMM helpers ----------------------------------
__device__ __forceinline__ void ldsm4(unsigned (&r)[4], unsigned addr) {
    asm volatile("ldmatrix.sync.aligned.m8n8.x4.shared.b16 {%0,%1,%2,%3}, [%4];"
        : "=r"(r[0]), "=r"(r[1]), "=r"(r[2]), "=r"(r[3]) : "r"(addr));
}
__device__ __forceinline__ void ldsm4t(unsigned (&r)[4], unsigned addr) {
    asm volatile("ldmatrix.sync.aligned.m8n8.x4.trans.shared.b16 {%0,%1,%2,%3}, [%4];"
        : "=r"(r[0]), "=r"(r[1]), "=r"(r[2]), "=r"(r[3]) : "r"(addr));
}
__device__ __forceinline__ void mma_bf16(float (&c)[4], const unsigned (&a)[4],
                                         unsigned b0, unsigned b1) {
    asm volatile("mma.sync.aligned.m16n8k16.row.col.f32.bf16.bf16.f32 "
        "{%0,%1,%2,%3}, {%4,%5,%6,%7}, {%8,%9}, {%0,%1,%2,%3};"
        : "+f"(c[0]), "+f"(c[1]), "+f"(c[2]), "+f"(c[3])
        : "r"(a[0]), "r"(a[1]), "r"(a[2]), "r"(a[3]), "r"(b0), "r"(b1));
}

// C = act([A|...] @ Wb) -> bf16x2 packed output.
// Af non-null: A is fp32 (gating path), converted during smem load.
// statacc non-null: fused BN stats (per-col sum / sumsq of pre-rounding fp32).
#define A_STRIDE 56
#define B_STRIDE 136
__global__ __launch_bounds__(256, 2)
void gemm_bf16_kernel(const __nv_bfloat16* __restrict__ A0,
                      const __nv_bfloat16* __restrict__ A1,
                      const __nv_bfloat16* __restrict__ A2,
                      const float* __restrict__ Af,
                      const __nv_bfloat16* __restrict__ Wb,
                      const float* __restrict__ bias,
                      unsigned int* __restrict__ outb,
                      float* __restrict__ statacc,
                      int nrows, int ktiles, int act) {
    __shared__ __align__(16) unsigned short As[128 * A_STRIDE];
    __shared__ __align__(16) unsigned short Bs[32 * B_STRIDE];
    __shared__ float smstat[256];

    int tid  = threadIdx.x;
    int lane = tid & 31;
    int wid  = tid >> 5;
    int m_warp = (wid >> 1) * 32;
    int n_warp = (wid & 1) * 64;
    int r0 = blockIdx.x * 128;

    unsigned as_base = (unsigned)__cvta_generic_to_shared(As);
    unsigned bs_base = (unsigned)__cvta_generic_to_shared(Bs);

    float acc[2][8][4];
    #pragma unroll
    for (int mt = 0; mt < 2; mt++)
        #pragma unroll
        for (int nt = 0; nt < 8; nt++)
            #pragma unroll
            for (int k = 0; k < 4; k++) acc[mt][nt][k] = 0.f;

    for (int kt = 0; kt < ktiles; kt++) {
        int seg = kt >> 2;
        const __nv_bfloat16* Ap = (seg == 0) ? A0 : ((seg == 1) ? A1 : A2);
        int kk = (kt & 3) * 32;

        // A tile [128 x 32] bf16 (convert from fp32 if Af path)
        #pragma unroll
        for (int it = 0; it < 2; it++) {
            int idx = tid + it * 256;
            int row = idx >> 2;
            int ch  = idx & 3;
            int gr  = r0 + row;
            uint4 v = make_uint4(0u, 0u, 0u, 0u);
            if (Af) {
                if (gr < nrows) {
                    float4 u0 = *(const float4*)(Af + gr * 128 + kk + ch * 8);
                    float4 u1 = *(const float4*)(Af + gr * 128 + kk + ch * 8 + 4);
                    __nv_bfloat162 p0 = __float22bfloat162_rn(make_float2(u0.x, u0.y));
                    __nv_bfloat162 p1 = __float22bfloat162_rn(make_float2(u0.z, u0.w));
                    __nv_bfloat162 p2 = __float22bfloat162_rn(make_float2(u1.x, u1.y));
                    __nv_bfloat162 p3 = __float22bfloat162_rn(make_float2(u1.z, u1.w));
                    v = make_uint4(*(unsigned*)&p0, *(unsigned*)&p1,
                                   *(unsigned*)&p2, *(unsigned*)&p3);
                }
            } else if (gr < nrows) {
                v = *(const uint4*)(Ap + gr * 128 + kk + ch * 8);
            }
            *(uint4*)(As + row * A_STRIDE + ch * 8) = v;
        }
        // B tile [32 x 128] bf16
        #pragma unroll
        for (int it = 0; it < 2; it++) {
            int idx = tid + it * 256;
            int row = idx >> 4;
            int ch  = idx & 15;
            uint4 v = *(const uint4*)(Wb + (kt * 32 + row) * 128 + ch * 8);
            *(uint4*)(Bs + row * B_STRIDE + ch * 8) = v;
        }
        __syncthreads();

        #pragma unroll
        for (int ksub = 0; ksub < 2; ksub++) {
            unsigned a[2][4];
            #pragma unroll
            for (int mt = 0; mt < 2; mt++) {
                unsigned addr = as_base +
                    ((m_warp + mt * 16 + (lane & 15)) * A_STRIDE +
                     ksub * 16 + (lane >> 4) * 8) * 2;
                ldsm4(a[mt], addr);
            }
            unsigned b[4][4];
            #pragma unroll
            for (int nt2 = 0; nt2 < 4; nt2++) {
                unsigned addr = bs_base +
                    ((ksub * 16 + (lane & 15)) * B_STRIDE +
                     n_warp + nt2 * 16 + (lane >> 4) * 8) * 2;
                ldsm4t(b[nt2], addr);
            }
            #pragma unroll
            for (int mt = 0; mt < 2; mt++)
                #pragma unroll
                for (int nt = 0; nt < 8; nt++)
                    mma_bf16(acc[mt][nt], a[mt],
                             b[nt >> 1][(nt & 1) * 2],
                             b[nt >> 1][(nt & 1) * 2 + 1]);
        }
        __syncthreads();
    }

    // ---------------- epilogue -------------------------------------------
    int g  = lane >> 2;
    int t4 = lane & 3;
    if (statacc) {
        smstat[tid] = 0.f;
        __syncthreads();
    }
    #pragma unroll
    for (int mt = 0; mt < 2; mt++) {
        int row0 = r0 + m_warp + mt * 16 + g;
        bool v0 = row0 < nrows;
        bool v1 = row0 + 8 < nrows;
        #pragma unroll
        for (int nt = 0; nt < 8; nt++) {
            int col = n_warp + nt * 8 + 2 * t4;
            float c0 = acc[mt][nt][0], c1 = acc[mt][nt][1];
            float c2 = acc[mt][nt][2], c3 = acc[mt][nt][3];
            if (act) {
                float b0 = bias[col], b1 = bias[col + 1];
                c0 = 1.f / (1.f + __expf(-(c0 + b0)));
                c1 = 1.f / (1.f + __expf(-(c1 + b1)));
                c2 = 1.f / (1.f + __expf(-(c2 + b0)));
                c3 = 1.f / (1.f + __expf(-(c3 + b1)));
            }
            if (statacc) {
                float a0 = v0 ? c0 : 0.f, a1 = v0 ? c1 : 0.f;
                float a2 = v1 ? c2 : 0.f, a3 = v1 ? c3 : 0.f;
                float s0 = a0 + a2, s1 = a1 + a3;
                float q0 = a0 * a0 + a2 * a2, q1 = a1 * a1 + a3 * a3;
                #pragma unroll
                for (int m = 4; m < 32; m <<= 1) {
                    s0 += __shfl_xor_sync(0xffffffffu, s0, m);
                    s1 += __shfl_xor_sync(0xffffffffu, s1, m);
                    q0 += __shfl_xor_sync(0xffffffffu, q0, m);
                    q1 += __shfl_xor_sync(0xffffffffu, q1, m);
                }
                if (g == 0) {
                    atomicAdd(&smstat[col], s0);
                    atomicAdd(&smstat[col + 1], s1);
                    atomicAdd(&smstat[128 + col], q0);
                    atomicAdd(&smstat[128 + col + 1], q1);
                }
            }
            if (v0) {
                __nv_bfloat162 p = __float22bfloat162_rn(make_float2(c0, c1));
                outb[row0 * 64 + (col >> 1)] = *(unsigned*)&p;
            }
            if (v1) {
                __nv_bfloat162 p = __float22bfloat162_rn(make_float2(c2, c3));
                outb[(row0 + 8) * 64 + (col >> 1)] = *(unsigned*)&p;
            }
        }
    }
    if (statacc) {
        __syncthreads();
        atomicAdd(&statacc[tid], smstat[tid]);
    }
}

// ---------------- BN apply + ReLU (bf16 z in, optional bf16 out, colsum) ----
__global__ void bn_apply_kernel(const unsigned int* __restrict__ z2,
                                unsigned int* __restrict__ hout2,
                                const float* __restrict__ acc,
                                const float* __restrict__ gamma,
                                const float* __restrict__ beta,
                                int n, int docol) {
    int cp  = threadIdx.x & 63;        // channel pair
    int sub = threadIdx.x >> 6;        // 0..3
    int c0 = cp * 2, c1 = c0 + 1;
    float inv_n = 1.f / (float)n;
    float mu0 = acc[c0] * inv_n, mu1 = acc[c1] * inv_n;
    float va0 = acc[128 + c0] * inv_n - mu0 * mu0;
    float va1 = acc[128 + c1] * inv_n - mu1 * mu1;
    float s0 = rsqrtf(va0 + BN_EPS) * gamma[c0];
    float s1 = rsqrtf(va1 + BN_EPS) * gamma[c1];
    float h0 = beta[c0] - mu0 * s0;
    float h1 = beta[c1] - mu1 * s1;
    int r0 = blockIdx.x * 512;
    int r1 = min(r0 + 512, n);
    float cs0 = 0.f, cs1 = 0.f;
    for (int r = r0 + sub; r < r1; r += 4) {
        unsigned p = z2[r * 64 + cp];
        float2 f = __bfloat1622float2(*(__nv_bfloat162*)&p);
        float v0 = fmaxf(fmaf(f.x, s0, h0), 0.f);
        float v1 = fmaxf(fmaf(f.y, s1, h1), 0.f);
        if (hout2) {
            __nv_bfloat162 o = __float22bfloat162_rn(make_float2(v0, v1));
            hout2[r * 64 + cp] = *(unsigned*)&o;
        }
        cs0 += v0;
        cs1 += v1;
    }
    if (docol) {
        atomicAdd(&g_colsum[c0], cs0);
        atomicAdd(&g_colsum[c1], cs1);
    }
}

// ---------------- readout: out = colmean(h) @ Wd + bd -----------------------
__global__ void final_kernel(const float* __restrict__ Wd,
                             const float* __restrict__ bd,
                             float* __restrict__ out, int n) {
    int j = threadIdx.x;
    float inv_n = 1.f / (float)n;
    float acc = bd[j];
    #pragma unroll 4
    for (int c = 0; c < D; c++)
        acc = fmaf(__ldg(&g_colsum[c]) * inv_n, Wd[c * 256 + j], acc);
    out[j] = acc;
}

// ---------------- launch ----------------------------------------------------
extern "C" void kernel_launch(void* const* d_in, const int* in_sizes, int n_in,
                              void* d_out, int out_size) {
    const float* features = (const float*)d_in[0];
    const int*   src      = (const int*)  d_in[1];
    const int*   dst      = (const int*)  d_in[2];
    const float* Wg  = (const float*)d_in[3];
    const float* bg  = (const float*)d_in[4];
    const float* Wc1 = (const float*)d_in[5];
    const float* g1  = (const float*)d_in[6];
    const float* b1  = (const float*)d_in[7];
    const float* Wc2 = (const float*)d_in[8];
    const float* g2  = (const float*)d_in[9];
    const float* b2  = (const float*)d_in[10];
    const float* Wd  = (const float*)d_in[11];
    const float* bd  = (const float*)d_in[12];
    float* out = (float*)d_out;

    int N = in_sizes[0] / D;
    int E = in_sizes[1];

    void* p;
    __nv_bfloat16 *hb0, *hb1, *hb2, *wb;
    unsigned int* zb;
    float* bnacc;
    cudaGetSymbolAddress(&p, g_hb0);   hb0 = (__nv_bfloat16*)p;
    cudaGetSymbolAddress(&p, g_hb1);   hb1 = (__nv_bfloat16*)p;
    cudaGetSymbolAddress(&p, g_hb2);   hb2 = (__nv_bfloat16*)p;
    cudaGetSymbolAddress(&p, g_wb);    wb  = (__nv_bfloat16*)p;
    cudaGetSymbolAddress(&p, g_zb);    zb  = (unsigned int*)p;
    cudaGetSymbolAddress(&p, g_bnacc); bnacc = (float*)p;

    int gb  = (N + 127) / 128;
    int bnb = (N + 511) / 512;
    int spb = (N + 7) / 8;
    int nsb = (N + 1023) / 1024;
    int eb2 = ((E >> 1) + 255) / 256;

    // graph structure + weight conversion
    init_kernel<<<448, 256>>>(N, Wg, Wc1, Wc2);
    count_deg_kernel<<<eb2, 256>>>(dst, E);
    scanA_kernel<<<nsb, 1024>>>(N);
    scanC_kernel<<<(N + 255) / 256, 256>>>(N, E, nsb);
    scatter_kernel<<<eb2, 256>>>(src, dst, E);

    // gating: hb0 = sigmoid(features @ Wg + bg)  (fp32 A, bf16 out)
    gemm_bf16_kernel<<<gb, 256>>>(nullptr, nullptr, nullptr, features, wb, bg,
                                  (unsigned int*)hb0, nullptr, N, 4, 1);

    // ---- layer 1 ----
    spmm_kernel<<<spb, 256>>>((const uint2*)hb0, (uint2*)hb1, N);
    spmm_kernel<<<spb, 256>>>((const uint2*)hb1, (uint2*)hb2, N);
    gemm_bf16_kernel<<<gb, 256>>>(hb0, hb1, hb2, nullptr, wb + 16384, nullptr,
                                  zb, bnacc, N, 12, 0);
    bn_apply_kernel<<<bnb, 256>>>(zb, (unsigned int*)hb0, bnacc, g1, b1, N, 0);

    // ---- layer 2 ----
    spmm_kernel<<<spb, 256>>>((const uint2*)hb0, (uint2*)hb1, N);
    spmm_kernel<<<spb, 256>>>((const uint2*)hb1, (uint2*)hb2, N);
    gemm_bf16_kernel<<<gb, 256>>>(hb0, hb1, hb2, nullptr, wb + 65536, nullptr,
                                  zb, bnacc + 256, N, 12, 0);
    bn_apply_kernel<<<bnb, 256>>>(zb, nullptr, bnacc + 256, g2, b2, N, 1);

    // readout
    final_kernel<<<1, 256>>>(Wd, bd, out, N);
}

// round 7
// speedup vs baseline: 2.4525x; 1.0342x over previous
#include <cuda_runtime.h>
#include <cuda_bf16.h>
#include <math.h>

#define MAXN 50000
#define MAXE 800000
#define D    128
#define BN_EPS 1e-5f

// ---------------- scratch (static __device__ — no allocations) -------------
__device__ __align__(16) __nv_bfloat16 g_hb0[MAXN * D];
__device__ __align__(16) __nv_bfloat16 g_hb1[MAXN * D];
__device__ __align__(16) __nv_bfloat16 g_hb2[MAXN * D];
__device__ __align__(16) __nv_bfloat16 g_wb[114688];     // Wg|Wc1|Wc2 bf16
__device__ __align__(16) unsigned int g_zb[MAXN * 64];   // z as bf16x2 pairs
__device__ float g_norm[MAXN];
__device__ int   g_deg[MAXN];
__device__ int   g_rowptr[MAXN + 1];
__device__ int   g_cursor[MAXN];
__device__ int   g_csrsrc[MAXE];
__device__ int   g_blocksum[64];
__device__ float g_bnacc[512];
__device__ float g_colsum[128];

// ---------------- init: zero accumulators + convert weights ----------------
__global__ void init_kernel(int n, const float* __restrict__ Wg,
                            const float* __restrict__ Wc1,
                            const float* __restrict__ Wc2) {
    int i = blockIdx.x * blockDim.x + threadIdx.x;
    if (i < n)   g_deg[i] = 0;
    if (i < 512) g_bnacc[i] = 0.f;
    if (i < 128) g_colsum[i] = 0.f;
    if (i < 16384)       g_wb[i] = __float2bfloat16(Wg[i]);
    else if (i < 65536)  g_wb[i] = __float2bfloat16(Wc1[i - 16384]);
    else if (i < 114688) g_wb[i] = __float2bfloat16(Wc2[i - 65536]);
}

// ---------------- degree histogram (2 edges/thread) -------------------------
__global__ void count_deg_kernel(const int* __restrict__ dst, int e) {
    int i = blockIdx.x * blockDim.x + threadIdx.x;
    int half = e >> 1;
    if (i < half) {
        int2 d = ((const int2*)dst)[i];
        atomicAdd(&g_deg[d.x], 1);
        atomicAdd(&g_deg[d.y], 1);
    }
    if (i == 0 && (e & 1)) atomicAdd(&g_deg[dst[e - 1]], 1);
}

// ---------------- scan phase A ----------------------------------------------
__global__ void scanA_kernel(int n) {
    __shared__ int sm[1024];
    int t = threadIdx.x;
    int i = blockIdx.x * 1024 + t;
    int v = (i < n) ? g_deg[i] : 0;
    if (i < n) g_norm[i] = rsqrtf((float)(v > 0 ? v : 1));
    sm[t] = v;
    __syncthreads();
    #pragma unroll
    for (int off = 1; off < 1024; off <<= 1) {
        int x = sm[t];
        if (t >= off) x += sm[t - off];
        __syncthreads();
        sm[t] = x;
        __syncthreads();
    }
    if (i < n) g_rowptr[i] = sm[t] - v;
    if (t == 1023) g_blocksum[blockIdx.x] = sm[t];
}

// ---------------- scan phase C ----------------------------------------------
__global__ void scanC_kernel(int n, int e, int nb) {
    __shared__ int pref[64];
    int t = threadIdx.x;
    if (t < 64) {
        int s = 0;
        for (int j = 0; j < t && j < nb; j++) s += g_blocksum[j];
        pref[t] = s;
    }
    __syncthreads();
    int i = blockIdx.x * blockDim.x + t;
    if (i < n) {
        int r = g_rowptr[i] + pref[i >> 10];
        g_rowptr[i] = r;
        g_cursor[i] = r;
    }
    if (i == 0) g_rowptr[n] = e;
}

// ---------------- CSR scatter (2 edges/thread) ------------------------------
__global__ void scatter_kernel(const int* __restrict__ src,
                               const int* __restrict__ dst, int e) {
    int i = blockIdx.x * blockDim.x + threadIdx.x;
    int half = e >> 1;
    if (i < half) {
        int2 d = ((const int2*)dst)[i];
        int2 s = ((const int2*)src)[i];
        int p0 = atomicAdd(&g_cursor[d.x], 1);
        g_csrsrc[p0] = s.x;
        int p1 = atomicAdd(&g_cursor[d.y], 1);
        g_csrsrc[p1] = s.y;
    }
    if (i == 0 && (e & 1)) {
        int p = atomicAdd(&g_cursor[dst[e - 1]], 1);
        g_csrsrc[p] = src[e - 1];
    }
}

// ---------------- warp-per-node SpMM (smem edge staging, no shfl) -----------
// hout[v] = norm[v] * sum_{s in CSR[v]} norm[s] * hin[s]
__global__ __launch_bounds__(256)
void spmm_kernel(const uint2* __restrict__ hin,
                 uint2* __restrict__ hout, int n) {
    __shared__ uint2 sed[8][32];          // per-warp (src*32, norm bits)
    int wslot = threadIdx.x >> 5;
    int node = blockIdx.x * 8 + wslot;
    int lane = threadIdx.x & 31;
    if (node >= n) return;
    int beg = g_rowptr[node], end = g_rowptr[node + 1];
    const uint2* hp = hin + lane;         // pre-biased by lane
    float4 acc = make_float4(0.f, 0.f, 0.f, 0.f);
    for (int chunk = beg; chunk < end; chunk += 32) {
        int cnt = min(32, end - chunk);
        if (lane < cnt) {
            int s = g_csrsrc[chunk + lane];
            sed[wslot][lane] = make_uint2((unsigned)(s * 32),
                                          __float_as_uint(g_norm[s]));
        }
        __syncwarp();
        #pragma unroll 4
        for (int j = 0; j < cnt; j++) {
            uint2 e = sed[wslot][j];       // LDS.64 broadcast
            float w = __uint_as_float(e.y);
            uint2 p = __ldg(&hp[e.x]);
            float2 f0 = __bfloat1622float2(*(__nv_bfloat162*)&p.x);
            float2 f1 = __bfloat1622float2(*(__nv_bfloat162*)&p.y);
            acc.x = fmaf(f0.x, w, acc.x);
            acc.y = fmaf(f0.y, w, acc.y);
            acc.z = fmaf(f1.x, w, acc.z);
            acc.w = fmaf(f1.y, w, acc.w);
        }
        __syncwarp();
    }
    float nv = g_norm[node];
    __nv_bfloat162 o0 = __float22bfloat162_rn(make_float2(acc.x * nv, acc.y * nv));
    __nv_bfloat162 o1 = __float22bfloat162_rn(make_float2(acc.z * nv, acc.w * nv));
    hout[node * 32 + lane] = make_uint2(*(unsigned*)&o0, *(unsigned*)&o1);
}

// ---------------- tensor-core GEMM helpers ----------------------------------
__device__ __forceinline__ void ldsm4(unsigned (&r)[4], unsigned addr) {
    asm volatile("ldmatrix.sync.aligned.m8n8.x4.shared.b16 {%0,%1,%2,%3}, [%4];"
        : "=r"(r[0]), "=r"(r[1]), "=r"(r[2]), "=r"(r[3]) : "r"(addr));
}
__device__ __forceinline__ void ldsm4t(unsigned (&r)[4], unsigned addr) {
    asm volatile("ldmatrix.sync.aligned.m8n8.x4.trans.shared.b16 {%0,%1,%2,%3}, [%4];"
        : "=r"(r[0]), "=r"(r[1]), "=r"(r[2]), "=r"(r[3]) : "r"(addr));
}
__device__ __forceinline__ void mma_bf16(float (&c)[4], const unsigned (&a)[4],
                                         unsigned b0, unsigned b1) {
    asm volatile("mma.sync.aligned.m16n8k16.row.col.f32.bf16.bf16.f32 "
        "{%0,%1,%2,%3}, {%4,%5,%6,%7}, {%8,%9}, {%0,%1,%2,%3};"
        : "+f"(c[0]), "+f"(c[1]), "+f"(c[2]), "+f"(c[3])
        : "r"(a[0]), "r"(a[1]), "r"(a[2]), "r"(a[3]), "r"(b0), "r"(b1));
}

// C = act([A|...] @ Wb) -> bf16x2 packed output.
// Af non-null: A is fp32 (gating path), converted during smem load.
// statacc non-null: fused BN stats (per-col sum / sumsq of pre-rounding fp32).
#define A_STRIDE 56
#define B_STRIDE 136
__global__ __launch_bounds__(256, 2)
void gemm_bf16_kernel(const __nv_bfloat16* __restrict__ A0,
                      const __nv_bfloat16* __restrict__ A1,
                      const __nv_bfloat16* __restrict__ A2,
                      const float* __restrict__ Af,
                      const __nv_bfloat16* __restrict__ Wb,
                      const float* __restrict__ bias,
                      unsigned int* __restrict__ outb,
                      float* __restrict__ statacc,
                      int nrows, int ktiles, int act) {
    __shared__ __align__(16) unsigned short As[128 * A_STRIDE];
    __shared__ __align__(16) unsigned short Bs[32 * B_STRIDE];
    __shared__ float smstat[256];

    int tid  = threadIdx.x;
    int lane = tid & 31;
    int wid  = tid >> 5;
    int m_warp = (wid >> 1) * 32;
    int n_warp = (wid & 1) * 64;
    int r0 = blockIdx.x * 128;

    unsigned as_base = (unsigned)__cvta_generic_to_shared(As);
    unsigned bs_base = (unsigned)__cvta_generic_to_shared(Bs);

    float acc[2][8][4];
    #pragma unroll
    for (int mt = 0; mt < 2; mt++)
        #pragma unroll
        for (int nt = 0; nt < 8; nt++)
            #pragma unroll
            for (int k = 0; k < 4; k++) acc[mt][nt][k] = 0.f;

    for (int kt = 0; kt < ktiles; kt++) {
        int seg = kt >> 2;
        const __nv_bfloat16* Ap = (seg == 0) ? A0 : ((seg == 1) ? A1 : A2);
        int kk = (kt & 3) * 32;

        // A tile [128 x 32] bf16 (convert from fp32 if Af path)
        #pragma unroll
        for (int it = 0; it < 2; it++) {
            int idx = tid + it * 256;
            int row = idx >> 2;
            int ch  = idx & 3;
            int gr  = r0 + row;
            uint4 v = make_uint4(0u, 0u, 0u, 0u);
            if (Af) {
                if (gr < nrows) {
                    float4 u0 = *(const float4*)(Af + gr * 128 + kk + ch * 8);
                    float4 u1 = *(const float4*)(Af + gr * 128 + kk + ch * 8 + 4);
                    __nv_bfloat162 p0 = __float22bfloat162_rn(make_float2(u0.x, u0.y));
                    __nv_bfloat162 p1 = __float22bfloat162_rn(make_float2(u0.z, u0.w));
                    __nv_bfloat162 p2 = __float22bfloat162_rn(make_float2(u1.x, u1.y));
                    __nv_bfloat162 p3 = __float22bfloat162_rn(make_float2(u1.z, u1.w));
                    v = make_uint4(*(unsigned*)&p0, *(unsigned*)&p1,
                                   *(unsigned*)&p2, *(unsigned*)&p3);
                }
            } else if (gr < nrows) {
                v = *(const uint4*)(Ap + gr * 128 + kk + ch * 8);
            }
            *(uint4*)(As + row * A_STRIDE + ch * 8) = v;
        }
        // B tile [32 x 128] bf16
        #pragma unroll
        for (int it = 0; it < 2; it++) {
            int idx = tid + it * 256;
            int row = idx >> 4;
            int ch  = idx & 15;
            uint4 v = *(const uint4*)(Wb + (kt * 32 + row) * 128 + ch * 8);
            *(uint4*)(Bs + row * B_STRIDE + ch * 8) = v;
        }
        __syncthreads();

        #pragma unroll
        for (int ksub = 0; ksub < 2; ksub++) {
            unsigned a[2][4];
            #pragma unroll
            for (int mt = 0; mt < 2; mt++) {
                unsigned addr = as_base +
                    ((m_warp + mt * 16 + (lane & 15)) * A_STRIDE +
                     ksub * 16 + (lane >> 4) * 8) * 2;
                ldsm4(a[mt], addr);
            }
            unsigned b[4][4];
            #pragma unroll
            for (int nt2 = 0; nt2 < 4; nt2++) {
                unsigned addr = bs_base +
                    ((ksub * 16 + (lane & 15)) * B_STRIDE +
                     n_warp + nt2 * 16 + (lane >> 4) * 8) * 2;
                ldsm4t(b[nt2], addr);
            }
            #pragma unroll
            for (int mt = 0; mt < 2; mt++)
                #pragma unroll
                for (int nt = 0; nt < 8; nt++)
                    mma_bf16(acc[mt][nt], a[mt],
                             b[nt >> 1][(nt & 1) * 2],
                             b[nt >> 1][(nt & 1) * 2 + 1]);
        }
        __syncthreads();
    }

    // ---------------- epilogue -------------------------------------------
    int g  = lane >> 2;
    int t4 = lane & 3;
    if (statacc) {
        smstat[tid] = 0.f;
        __syncthreads();
    }
    #pragma unroll
    for (int mt = 0; mt < 2; mt++) {
        int row0 = r0 + m_warp + mt * 16 + g;
        bool v0 = row0 < nrows;
        bool v1 = row0 + 8 < nrows;
        #pragma unroll
        for (int nt = 0; nt < 8; nt++) {
            int col = n_warp + nt * 8 + 2 * t4;
            float c0 = acc[mt][nt][0], c1 = acc[mt][nt][1];
            float c2 = acc[mt][nt][2], c3 = acc[mt][nt][3];
            if (act) {
                float b0 = bias[col], b1 = bias[col + 1];
                c0 = 1.f / (1.f + __expf(-(c0 + b0)));
                c1 = 1.f / (1.f + __expf(-(c1 + b1)));
                c2 = 1.f / (1.f + __expf(-(c2 + b0)));
                c3 = 1.f / (1.f + __expf(-(c3 + b1)));
            }
            if (statacc) {
                float a0 = v0 ? c0 : 0.f, a1 = v0 ? c1 : 0.f;
                float a2 = v1 ? c2 : 0.f, a3 = v1 ? c3 : 0.f;
                float s0 = a0 + a2, s1 = a1 + a3;
                float q0 = a0 * a0 + a2 * a2, q1 = a1 * a1 + a3 * a3;
                #pragma unroll
                for (int m = 4; m < 32; m <<= 1) {
                    s0 += __shfl_xor_sync(0xffffffffu, s0, m);
                    s1 += __shfl_xor_sync(0xffffffffu, s1, m);
                    q0 += __shfl_xor_sync(0xffffffffu, q0, m);
                    q1 += __shfl_xor_sync(0xffffffffu, q1, m);
                }
                if (g == 0) {
                    atomicAdd(&smstat[col], s0);
                    atomicAdd(&smstat[col + 1], s1);
                    atomicAdd(&smstat[128 + col], q0);
                    atomicAdd(&smstat[128 + col + 1], q1);
                }
            }
            if (v0) {
                __nv_bfloat162 p = __float22bfloat162_rn(make_float2(c0, c1));
                outb[row0 * 64 + (col >> 1)] = *(unsigned*)&p;
            }
            if (v1) {
                __nv_bfloat162 p = __float22bfloat162_rn(make_float2(c2, c3));
                outb[(row0 + 8) * 64 + (col >> 1)] = *(unsigned*)&p;
            }
        }
    }
    if (statacc) {
        __syncthreads();
        atomicAdd(&statacc[tid], smstat[tid]);
    }
}

// ---------------- BN apply + ReLU (bf16 z in, optional bf16 out, colsum) ----
__global__ void bn_apply_kernel(const unsigned int* __restrict__ z2,
                                unsigned int* __restrict__ hout2,
                                const float* __restrict__ acc,
                                const float* __restrict__ gamma,
                                const float* __restrict__ beta,
                                int n, int docol) {
    int cp  = threadIdx.x & 63;
    int sub = threadIdx.x >> 6;
    int c0 = cp * 2, c1 = c0 + 1;
    float inv_n = 1.f / (float)n;
    float mu0 = acc[c0] * inv_n, mu1 = acc[c1] * inv_n;
    float va0 = acc[128 + c0] * inv_n - mu0 * mu0;
    float va1 = acc[128 + c1] * inv_n - mu1 * mu1;
    float s0 = rsqrtf(va0 + BN_EPS) * gamma[c0];
    float s1 = rsqrtf(va1 + BN_EPS) * gamma[c1];
    float h0 = beta[c0] - mu0 * s0;
    float h1 = beta[c1] - mu1 * s1;
    int r0 = blockIdx.x * 512;
    int r1 = min(r0 + 512, n);
    float cs0 = 0.f, cs1 = 0.f;
    for (int r = r0 + sub; r < r1; r += 4) {
        unsigned p = z2[r * 64 + cp];
        float2 f = __bfloat1622float2(*(__nv_bfloat162*)&p);
        float v0 = fmaxf(fmaf(f.x, s0, h0), 0.f);
        float v1 = fmaxf(fmaf(f.y, s1, h1), 0.f);
        if (hout2) {
            __nv_bfloat162 o = __float22bfloat162_rn(make_float2(v0, v1));
            hout2[r * 64 + cp] = *(unsigned*)&o;
        }
        cs0 += v0;
        cs1 += v1;
    }
    if (docol) {
        atomicAdd(&g_colsum[c0], cs0);
        atomicAdd(&g_colsum[c1], cs1);
    }
}

// ---------------- readout: out = colmean(h) @ Wd + bd -----------------------
__global__ void final_kernel(const float* __restrict__ Wd,
                             const float* __restrict__ bd,
                             float* __restrict__ out, int n) {
    int j = threadIdx.x;
    float inv_n = 1.f / (float)n;
    float acc = bd[j];
    #pragma unroll 4
    for (int c = 0; c < D; c++)
        acc = fmaf(__ldg(&g_colsum[c]) * inv_n, Wd[c * 256 + j], acc);
    out[j] = acc;
}

// ---------------- launch ----------------------------------------------------
extern "C" void kernel_launch(void* const* d_in, const int* in_sizes, int n_in,
                              void* d_out, int out_size) {
    const float* features = (const float*)d_in[0];
    const int*   src      = (const int*)  d_in[1];
    const int*   dst      = (const int*)  d_in[2];
    const float* Wg  = (const float*)d_in[3];
    const float* bg  = (const float*)d_in[4];
    const float* Wc1 = (const float*)d_in[5];
    const float* g1  = (const float*)d_in[6];
    const float* b1  = (const float*)d_in[7];
    const float* Wc2 = (const float*)d_in[8];
    const float* g2  = (const float*)d_in[9];
    const float* b2  = (const float*)d_in[10];
    const float* Wd  = (const float*)d_in[11];
    const float* bd  = (const float*)d_in[12];
    float* out = (float*)d_out;

    int N = in_sizes[0] / D;
    int E = in_sizes[1];

    void* p;
    __nv_bfloat16 *hb0, *hb1, *hb2, *wb;
    unsigned int* zb;
    float* bnacc;
    cudaGetSymbolAddress(&p, g_hb0);   hb0 = (__nv_bfloat16*)p;
    cudaGetSymbolAddress(&p, g_hb1);   hb1 = (__nv_bfloat16*)p;
    cudaGetSymbolAddress(&p, g_hb2);   hb2 = (__nv_bfloat16*)p;
    cudaGetSymbolAddress(&p, g_wb);    wb  = (__nv_bfloat16*)p;
    cudaGetSymbolAddress(&p, g_zb);    zb  = (unsigned int*)p;
    cudaGetSymbolAddress(&p, g_bnacc); bnacc = (float*)p;

    int gb  = (N + 127) / 128;
    int bnb = (N + 511) / 512;
    int spb = (N + 7) / 8;
    int nsb = (N + 1023) / 1024;
    int eb2 = ((E >> 1) + 255) / 256;

    // graph structure + weight conversion
    init_kernel<<<448, 256>>>(N, Wg, Wc1, Wc2);
    count_deg_kernel<<<eb2, 256>>>(dst, E);
    scanA_kernel<<<nsb, 1024>>>(N);
    scanC_kernel<<<(N + 255) / 256, 256>>>(N, E, nsb);
    scatter_kernel<<<eb2, 256>>>(src, dst, E);

    // gating: hb0 = sigmoid(features @ Wg + bg)  (fp32 A, bf16 out)
    gemm_bf16_kernel<<<gb, 256>>>(nullptr, nullptr, nullptr, features, wb, bg,
                                  (unsigned int*)hb0, nullptr, N, 4, 1);

    // ---- layer 1 ----
    spmm_kernel<<<spb, 256>>>((const uint2*)hb0, (uint2*)hb1, N);
    spmm_kernel<<<spb, 256>>>((const uint2*)hb1, (uint2*)hb2, N);
    gemm_bf16_kernel<<<gb, 256>>>(hb0, hb1, hb2, nullptr, wb + 16384, nullptr,
                                  zb, bnacc, N, 12, 0);
    bn_apply_kernel<<<bnb, 256>>>(zb, (unsigned int*)hb0, bnacc, g1, b1, N, 0);

    // ---- layer 2 ----
    spmm_kernel<<<spb, 256>>>((const uint2*)hb0, (uint2*)hb1, N);
    spmm_kernel<<<spb, 256>>>((const uint2*)hb1, (uint2*)hb2, N);
    gemm_bf16_kernel<<<gb, 256>>>(hb0, hb1, hb2, nullptr, wb + 65536, nullptr,
                                  zb, bnacc + 256, N, 12, 0);
    bn_apply_kernel<<<bnb, 256>>>(zb, nullptr, bnacc + 256, g2, b2, N, 1);

    // readout
    final_kernel<<<1, 256>>>(Wd, bd, out, N);
}

// round 9
// speedup vs baseline: 2.5271x; 1.0304x over previous
#include <cuda_runtime.h>
#include <cuda_bf16.h>
#include <math.h>

#define MAXN 50000
#define MAXE 800000
#define D    128
#define BN_EPS 1e-5f

// ---------------- scratch (static __device__ — no allocations) -------------
__device__ __align__(16) __nv_bfloat16 g_hb0[MAXN * D];
__device__ __align__(16) __nv_bfloat16 g_hb1[MAXN * D];
__device__ __align__(16) __nv_bfloat16 g_hb2[MAXN * D];
__device__ __align__(16) __nv_bfloat16 g_wb[114688];     // Wg|Wc1|Wc2 bf16
__device__ __align__(16) unsigned int g_zb[MAXN * 64];   // z as bf16x2 pairs
__device__ float g_norm[MAXN];
__device__ int   g_deg[MAXN];
__device__ int   g_rowptr[MAXN + 1];
__device__ int   g_cursor[MAXN];
__device__ __align__(16) uint2 g_csredge[MAXE];          // {src*16, norm bits}
__device__ int   g_blocksum[64];
__device__ float g_bnacc[512];
__device__ float g_colsum[128];

// ---------------- init: zero accumulators + convert weights ----------------
__global__ void init_kernel(int n, const float* __restrict__ Wg,
                            const float* __restrict__ Wc1,
                            const float* __restrict__ Wc2) {
    int i = blockIdx.x * blockDim.x + threadIdx.x;
    if (i < n)   g_deg[i] = 0;
    if (i < 512) g_bnacc[i] = 0.f;
    if (i < 128) g_colsum[i] = 0.f;
    if (i < 16384)       g_wb[i] = __float2bfloat16(Wg[i]);
    else if (i < 65536)  g_wb[i] = __float2bfloat16(Wc1[i - 16384]);
    else if (i < 114688) g_wb[i] = __float2bfloat16(Wc2[i - 65536]);
}

// ---------------- degree histogram (2 edges/thread) -------------------------
__global__ void count_deg_kernel(const int* __restrict__ dst, int e) {
    int i = blockIdx.x * blockDim.x + threadIdx.x;
    int half = e >> 1;
    if (i < half) {
        int2 d = ((const int2*)dst)[i];
        atomicAdd(&g_deg[d.x], 1);
        atomicAdd(&g_deg[d.y], 1);
    }
    if (i == 0 && (e & 1)) atomicAdd(&g_deg[dst[e - 1]], 1);
}

// ---------------- scan phase A ----------------------------------------------
__global__ void scanA_kernel(int n) {
    __shared__ int sm[1024];
    int t = threadIdx.x;
    int i = blockIdx.x * 1024 + t;
    int v = (i < n) ? g_deg[i] : 0;
    if (i < n) g_norm[i] = rsqrtf((float)(v > 0 ? v : 1));
    sm[t] = v;
    __syncthreads();
    #pragma unroll
    for (int off = 1; off < 1024; off <<= 1) {
        int x = sm[t];
        if (t >= off) x += sm[t - off];
        __syncthreads();
        sm[t] = x;
        __syncthreads();
    }
    if (i < n) g_rowptr[i] = sm[t] - v;
    if (t == 1023) g_blocksum[blockIdx.x] = sm[t];
}

// ---------------- scan phase C ----------------------------------------------
__global__ void scanC_kernel(int n, int e, int nb) {
    __shared__ int pref[64];
    int t = threadIdx.x;
    if (t < 64) {
        int s = 0;
        for (int j = 0; j < t && j < nb; j++) s += g_blocksum[j];
        pref[t] = s;
    }
    __syncthreads();
    int i = blockIdx.x * blockDim.x + t;
    if (i < n) {
        int r = g_rowptr[i] + pref[i >> 10];
        g_rowptr[i] = r;
        g_cursor[i] = r;
    }
    if (i == 0) g_rowptr[n] = e;
}

// ---------------- CSR scatter: fused edge records {src*16, norm(src)} ------
__global__ void scatter_kernel(const int* __restrict__ src,
                               const int* __restrict__ dst, int e) {
    int i = blockIdx.x * blockDim.x + threadIdx.x;
    int half = e >> 1;
    if (i < half) {
        int2 d = ((const int2*)dst)[i];
        int2 s = ((const int2*)src)[i];
        int p0 = atomicAdd(&g_cursor[d.x], 1);
        g_csredge[p0] = make_uint2((unsigned)(s.x * 16),
                                   __float_as_uint(g_norm[s.x]));
        int p1 = atomicAdd(&g_cursor[d.y], 1);
        g_csredge[p1] = make_uint2((unsigned)(s.y * 16),
                                   __float_as_uint(g_norm[s.y]));
    }
    if (i == 0 && (e & 1)) {
        int s = src[e - 1];
        int p = atomicAdd(&g_cursor[dst[e - 1]], 1);
        g_csredge[p] = make_uint2((unsigned)(s * 16),
                                  __float_as_uint(g_norm[s]));
    }
}

// ---------------- half-warp-per-node SpMM (uint4 rows, fused edges) ---------
// hout[v] = norm[v] * sum_{s in CSR[v]} norm[s] * hin[s]
__global__ __launch_bounds__(256)
void spmm_kernel(const uint4* __restrict__ hin,
                 uint4* __restrict__ hout, int n) {
    int hw   = threadIdx.x >> 4;          // half-warp slot 0..15
    int node = blockIdx.x * 16 + hw;
    int lane = threadIdx.x & 15;
    if (node >= n) return;
    int beg = g_rowptr[node], end = g_rowptr[node + 1];
    const uint4* hp = hin + lane;         // pre-biased by lane
    float a0 = 0.f, a1 = 0.f, a2 = 0.f, a3 = 0.f;
    float a4 = 0.f, a5 = 0.f, a6 = 0.f, a7 = 0.f;
    #pragma unroll 4
    for (int e = beg; e < end; e++) {
        uint2 em = __ldg(&g_csredge[e]);   // broadcast LDG.64
        uint4 p  = __ldg(&hp[em.x]);       // LDG.128 feature row slice
        float w  = __uint_as_float(em.y);
        float2 f0 = __bfloat1622float2(*(__nv_bfloat162*)&p.x);
        float2 f1 = __bfloat1622float2(*(__nv_bfloat162*)&p.y);
        float2 f2 = __bfloat1622float2(*(__nv_bfloat162*)&p.z);
        float2 f3 = __bfloat1622float2(*(__nv_bfloat162*)&p.w);
        a0 = fmaf(f0.x, w, a0);  a1 = fmaf(f0.y, w, a1);
        a2 = fmaf(f1.x, w, a2);  a3 = fmaf(f1.y, w, a3);
        a4 = fmaf(f2.x, w, a4);  a5 = fmaf(f2.y, w, a5);
        a6 = fmaf(f3.x, w, a6);  a7 = fmaf(f3.y, w, a7);
    }
    float nv = g_norm[node];
    __nv_bfloat162 o0 = __float22bfloat162_rn(make_float2(a0 * nv, a1 * nv));
    __nv_bfloat162 o1 = __float22bfloat162_rn(make_float2(a2 * nv, a3 * nv));
    __nv_bfloat162 o2 = __float22bfloat162_rn(make_float2(a4 * nv, a5 * nv));
    __nv_bfloat162 o3 = __float22bfloat162_rn(make_float2(a6 * nv, a7 * nv));
    hout[node * 16 + lane] = make_uint4(*(unsigned*)&o0, *(unsigned*)&o1,
                                        *(unsigned*)&o2, *(unsigned*)&o3);
}

// ---------------- tensor-core GEMM helpers ----------------------------------
__device__ __forceinline__ void ldsm4(unsigned (&r)[4], unsigned addr) {
    asm volatile("ldmatrix.sync.aligned.m8n8.x4.shared.b16 {%0,%1,%2,%3}, [%4];"
        : "=r"(r[0]), "=r"(r[1]), "=r"(r[2]), "=r"(r[3]) : "r"(addr));
}
__device__ __forceinline__ void ldsm4t(unsigned (&r)[4], unsigned addr) {
    asm volatile("ldmatrix.sync.aligned.m8n8.x4.trans.shared.b16 {%0,%1,%2,%3}, [%4];"
        : "=r"(r[0]), "=r"(r[1]), "=r"(r[2]), "=r"(r[3]) : "r"(addr));
}
__device__ __forceinline__ void mma_bf16(float (&c)[4], const unsigned (&a)[4],
                                         unsigned b0, unsigned b1) {
    asm volatile("mma.sync.aligned.m16n8k16.row.col.f32.bf16.bf16.f32 "
        "{%0,%1,%2,%3}, {%4,%5,%6,%7}, {%8,%9}, {%0,%1,%2,%3};"
        : "+f"(c[0]), "+f"(c[1]), "+f"(c[2]), "+f"(c[3])
        : "r"(a[0]), "r"(a[1]), "r"(a[2]), "r"(a[3]), "r"(b0), "r"(b1));
}

// C = act([A|...] @ Wb) -> bf16x2 packed output.
// Af non-null: A is fp32 (gating path), converted during smem load.
// statacc non-null: fused BN stats (per-col sum / sumsq of pre-rounding fp32).
#define A_STRIDE 56
#define B_STRIDE 136
__global__ __launch_bounds__(256, 2)
void gemm_bf16_kernel(const __nv_bfloat16* __restrict__ A0,
                      const __nv_bfloat16* __restrict__ A1,
                      const __nv_bfloat16* __restrict__ A2,
                      const float* __restrict__ Af,
                      const __nv_bfloat16* __restrict__ Wb,
                      const float* __restrict__ bias,
                      unsigned int* __restrict__ outb,
                      float* __restrict__ statacc,
                      int nrows, int ktiles, int act) {
    __shared__ __align__(16) unsigned short As[128 * A_STRIDE];
    __shared__ __align__(16) unsigned short Bs[32 * B_STRIDE];
    __shared__ float smstat[256];

    int tid  = threadIdx.x;
    int lane = tid & 31;
    int wid  = tid >> 5;
    int m_warp = (wid >> 1) * 32;
    int n_warp = (wid & 1) * 64;
    int r0 = blockIdx.x * 128;

    unsigned as_base = (unsigned)__cvta_generic_to_shared(As);
    unsigned bs_base = (unsigned)__cvta_generic_to_shared(Bs);

    float acc[2][8][4];
    #pragma unroll
    for (int mt = 0; mt < 2; mt++)
        #pragma unroll
        for (int nt = 0; nt < 8; nt++)
            #pragma unroll
            for (int k = 0; k < 4; k++) acc[mt][nt][k] = 0.f;

    for (int kt = 0; kt < ktiles; kt++) {
        int seg = kt >> 2;
        const __nv_bfloat16* Ap = (seg == 0) ? A0 : ((seg == 1) ? A1 : A2);
        int kk = (kt & 3) * 32;

        // A tile [128 x 32] bf16 (convert from fp32 if Af path)
        #pragma unroll
        for (int it = 0; it < 2; it++) {
            int idx = tid + it * 256;
            int row = idx >> 2;
            int ch  = idx & 3;
            int gr  = r0 + row;
            uint4 v = make_uint4(0u, 0u, 0u, 0u);
            if (Af) {
                if (gr < nrows) {
                    float4 u0 = *(const float4*)(Af + gr * 128 + kk + ch * 8);
                    float4 u1 = *(const float4*)(Af + gr * 128 + kk + ch * 8 + 4);
                    __nv_bfloat162 p0 = __float22bfloat162_rn(make_float2(u0.x, u0.y));
                    __nv_bfloat162 p1 = __float22bfloat162_rn(make_float2(u0.z, u0.w));
                    __nv_bfloat162 p2 = __float22bfloat162_rn(make_float2(u1.x, u1.y));
                    __nv_bfloat162 p3 = __float22bfloat162_rn(make_float2(u1.z, u1.w));
                    v = make_uint4(*(unsigned*)&p0, *(unsigned*)&p1,
                                   *(unsigned*)&p2, *(unsigned*)&p3);
                }
            } else if (gr < nrows) {
                v = *(const uint4*)(Ap + gr * 128 + kk + ch * 8);
            }
            *(uint4*)(As + row * A_STRIDE + ch * 8) = v;
        }
        // B tile [32 x 128] bf16
        #pragma unroll
        for (int it = 0; it < 2; it++) {
            int idx = tid + it * 256;
            int row = idx >> 4;
            int ch  = idx & 15;
            uint4 v = *(const uint4*)(Wb + (kt * 32 + row) * 128 + ch * 8);
            *(uint4*)(Bs + row * B_STRIDE + ch * 8) = v;
        }
        __syncthreads();

        #pragma unroll
        for (int ksub = 0; ksub < 2; ksub++) {
            unsigned a[2][4];
            #pragma unroll
            for (int mt = 0; mt < 2; mt++) {
                unsigned addr = as_base +
                    ((m_warp + mt * 16 + (lane & 15)) * A_STRIDE +
                     ksub * 16 + (lane >> 4) * 8) * 2;
                ldsm4(a[mt], addr);
            }
            unsigned b[4][4];
            #pragma unroll
            for (int nt2 = 0; nt2 < 4; nt2++) {
                unsigned addr = bs_base +
                    ((ksub * 16 + (lane & 15)) * B_STRIDE +
                     n_warp + nt2 * 16 + (lane >> 4) * 8) * 2;
                ldsm4t(b[nt2], addr);
            }
            #pragma unroll
            for (int mt = 0; mt < 2; mt++)
                #pragma unroll
                for (int nt = 0; nt < 8; nt++)
                    mma_bf16(acc[mt][nt], a[mt],
                             b[nt >> 1][(nt & 1) * 2],
                             b[nt >> 1][(nt & 1) * 2 + 1]);
        }
        __syncthreads();
    }

    // ---------------- epilogue -------------------------------------------
    int g  = lane >> 2;
    int t4 = lane & 3;
    if (statacc) {
        smstat[tid] = 0.f;
        __syncthreads();
    }
    #pragma unroll
    for (int mt = 0; mt < 2; mt++) {
        int row0 = r0 + m_warp + mt * 16 + g;
        bool v0 = row0 < nrows;
        bool v1 = row0 + 8 < nrows;
        #pragma unroll
        for (int nt = 0; nt < 8; nt++) {
            int col = n_warp + nt * 8 + 2 * t4;
            float c0 = acc[mt][nt][0], c1 = acc[mt][nt][1];
            float c2 = acc[mt][nt][2], c3 = acc[mt][nt][3];
            if (act) {
                float b0 = bias[col], b1 = bias[col + 1];
                c0 = 1.f / (1.f + __expf(-(c0 + b0)));
                c1 = 1.f / (1.f + __expf(-(c1 + b1)));
                c2 = 1.f / (1.f + __expf(-(c2 + b0)));
                c3 = 1.f / (1.f + __expf(-(c3 + b1)));
            }
            if (statacc) {
                float a0 = v0 ? c0 : 0.f, a1 = v0 ? c1 : 0.f;
                float a2 = v1 ? c2 : 0.f, a3 = v1 ? c3 : 0.f;
                float s0 = a0 + a2, s1 = a1 + a3;
                float q0 = a0 * a0 + a2 * a2, q1 = a1 * a1 + a3 * a3;
                #pragma unroll
                for (int m = 4; m < 32; m <<= 1) {
                    s0 += __shfl_xor_sync(0xffffffffu, s0, m);
                    s1 += __shfl_xor_sync(0xffffffffu, s1, m);
                    q0 += __shfl_xor_sync(0xffffffffu, q0, m);
                    q1 += __shfl_xor_sync(0xffffffffu, q1, m);
                }
                if (g == 0) {
                    atomicAdd(&smstat[col], s0);
                    atomicAdd(&smstat[col + 1], s1);
                    atomicAdd(&smstat[128 + col], q0);
                    atomicAdd(&smstat[128 + col + 1], q1);
                }
            }
            if (v0) {
                __nv_bfloat162 p = __float22bfloat162_rn(make_float2(c0, c1));
                outb[row0 * 64 + (col >> 1)] = *(unsigned*)&p;
            }
            if (v1) {
                __nv_bfloat162 p = __float22bfloat162_rn(make_float2(c2, c3));
                outb[(row0 + 8) * 64 + (col >> 1)] = *(unsigned*)&p;
            }
        }
    }
    if (statacc) {
        __syncthreads();
        atomicAdd(&statacc[tid], smstat[tid]);
    }
}

// ---------------- BN apply + ReLU (bf16 z in, optional bf16 out, colsum) ----
__global__ void bn_apply_kernel(const unsigned int* __restrict__ z2,
                                unsigned int* __restrict__ hout2,
                                const float* __restrict__ acc,
                                const float* __restrict__ gamma,
                                const float* __restrict__ beta,
                                int n, int docol) {
    int cp  = threadIdx.x & 63;
    int sub = threadIdx.x >> 6;
    int c0 = cp * 2, c1 = c0 + 1;
    float inv_n = 1.f / (float)n;
    float mu0 = acc[c0] * inv_n, mu1 = acc[c1] * inv_n;
    float va0 = acc[128 + c0] * inv_n - mu0 * mu0;
    float va1 = acc[128 + c1] * inv_n - mu1 * mu1;
    float s0 = rsqrtf(va0 + BN_EPS) * gamma[c0];
    float s1 = rsqrtf(va1 + BN_EPS) * gamma[c1];
    float h0 = beta[c0] - mu0 * s0;
    float h1 = beta[c1] - mu1 * s1;
    int r0 = blockIdx.x * 512;
    int r1 = min(r0 + 512, n);
    float cs0 = 0.f, cs1 = 0.f;
    for (int r = r0 + sub; r < r1; r += 4) {
        unsigned p = z2[r * 64 + cp];
        float2 f = __bfloat1622float2(*(__nv_bfloat162*)&p);
        float v0 = fmaxf(fmaf(f.x, s0, h0), 0.f);
        float v1 = fmaxf(fmaf(f.y, s1, h1), 0.f);
        if (hout2) {
            __nv_bfloat162 o = __float22bfloat162_rn(make_float2(v0, v1));
            hout2[r * 64 + cp] = *(unsigned*)&o;
        }
        cs0 += v0;
        cs1 += v1;
    }
    if (docol) {
        atomicAdd(&g_colsum[c0], cs0);
        atomicAdd(&g_colsum[c1], cs1);
    }
}

// ---------------- readout: out = colmean(h) @ Wd + bd -----------------------
__global__ void final_kernel(const float* __restrict__ Wd,
                             const float* __restrict__ bd,
                             float* __restrict__ out, int n) {
    int j = threadIdx.x;
    float inv_n = 1.f / (float)n;
    float acc = bd[j];
    #pragma unroll 4
    for (int c = 0; c < D; c++)
        acc = fmaf(__ldg(&g_colsum[c]) * inv_n, Wd[c * 256 + j], acc);
    out[j] = acc;
}

// ---------------- launch ----------------------------------------------------
extern "C" void kernel_launch(void* const* d_in, const int* in_sizes, int n_in,
                              void* d_out, int out_size) {
    const float* features = (const float*)d_in[0];
    const int*   src      = (const int*)  d_in[1];
    const int*   dst      = (const int*)  d_in[2];
    const float* Wg  = (const float*)d_in[3];
    const float* bg  = (const float*)d_in[4];
    const float* Wc1 = (const float*)d_in[5];
    const float* g1  = (const float*)d_in[6];
    const float* b1  = (const float*)d_in[7];
    const float* Wc2 = (const float*)d_in[8];
    const float* g2  = (const float*)d_in[9];
    const float* b2  = (const float*)d_in[10];
    const float* Wd  = (const float*)d_in[11];
    const float* bd  = (const float*)d_in[12];
    float* out = (float*)d_out;

    int N = in_sizes[0] / D;
    int E = in_sizes[1];

    void* p;
    __nv_bfloat16 *hb0, *hb1, *hb2, *wb;
    unsigned int* zb;
    float* bnacc;
    cudaGetSymbolAddress(&p, g_hb0);   hb0 = (__nv_bfloat16*)p;
    cudaGetSymbolAddress(&p, g_hb1);   hb1 = (__nv_bfloat16*)p;
    cudaGetSymbolAddress(&p, g_hb2);   hb2 = (__nv_bfloat16*)p;
    cudaGetSymbolAddress(&p, g_wb);    wb  = (__nv_bfloat16*)p;
    cudaGetSymbolAddress(&p, g_zb);    zb  = (unsigned int*)p;
    cudaGetSymbolAddress(&p, g_bnacc); bnacc = (float*)p;

    int gb  = (N + 127) / 128;
    int bnb = (N + 511) / 512;
    int spb = (N + 15) / 16;
    int nsb = (N + 1023) / 1024;
    int eb2 = ((E >> 1) + 255) / 256;

    // graph structure + weight conversion
    init_kernel<<<448, 256>>>(N, Wg, Wc1, Wc2);
    count_deg_kernel<<<eb2, 256>>>(dst, E);
    scanA_kernel<<<nsb, 1024>>>(N);
    scanC_kernel<<<(N + 255) / 256, 256>>>(N, E, nsb);
    scatter_kernel<<<eb2, 256>>>(src, dst, E);

    // gating: hb0 = sigmoid(features @ Wg + bg)  (fp32 A, bf16 out)
    gemm_bf16_kernel<<<gb, 256>>>(nullptr, nullptr, nullptr, features, wb, bg,
                                  (unsigned int*)hb0, nullptr, N, 4, 1);

    // ---- layer 1 ----
    spmm_kernel<<<spb, 256>>>((const uint4*)hb0, (uint4*)hb1, N);
    spmm_kernel<<<spb, 256>>>((const uint4*)hb1, (uint4*)hb2, N);
    gemm_bf16_kernel<<<gb, 256>>>(hb0, hb1, hb2, nullptr, wb + 16384, nullptr,
                                  zb, bnacc, N, 12, 0);
    bn_apply_kernel<<<bnb, 256>>>(zb, (unsigned int*)hb0, bnacc, g1, b1, N, 0);

    // ---- layer 2 ----
    spmm_kernel<<<spb, 256>>>((const uint4*)hb0, (uint4*)hb1, N);
    spmm_kernel<<<spb, 256>>>((const uint4*)hb1, (uint4*)hb2, N);
    gemm_bf16_kernel<<<gb, 256>>>(hb0, hb1, hb2, nullptr, wb + 65536, nullptr,
                                  zb, bnacc + 256, N, 12, 0);
    bn_apply_kernel<<<bnb, 256>>>(zb, nullptr, bnacc + 256, g2, b2, N, 1);

    // readout
    final_kernel<<<1, 256>>>(Wd, bd, out, N);
}

// round 10
// speedup vs baseline: 2.6331x; 1.0419x over previous
#include <cuda_runtime.h>
#include <cuda_bf16.h>
#include <math.h>

#define MAXN 50000
#define MAXE 800000
#define D    128
#define BN_EPS 1e-5f

// ---------------- scratch (static __device__ — no allocations) -------------
__device__ __align__(16) __nv_bfloat16 g_hb0[MAXN * D];
__device__ __align__(16) __nv_bfloat16 g_hb1[MAXN * D];
__device__ __align__(16) __nv_bfloat16 g_hb2[MAXN * D];
__device__ __align__(16) __nv_bfloat16 g_wb[114688];     // Wg|Wc1|Wc2 bf16
__device__ __align__(16) unsigned int g_zb[MAXN * 64];   // z as bf16x2 pairs
__device__ float g_norm[MAXN];
__device__ int   g_deg[MAXN];
__device__ int   g_rowptr[MAXN + 1];
__device__ int   g_cursor[MAXN];
__device__ __align__(16) uint2 g_csredge[MAXE];          // {src*16, norm bits}
__device__ int   g_blocksum[64];
__device__ float g_bnacc[512];
__device__ float g_colsum[128];

// ---------------- init: zero accumulators + convert weights ----------------
__global__ void init_kernel(int n, const float* __restrict__ Wg,
                            const float* __restrict__ Wc1,
                            const float* __restrict__ Wc2) {
    int i = blockIdx.x * blockDim.x + threadIdx.x;
    if (i < n)   g_deg[i] = 0;
    if (i < 512) g_bnacc[i] = 0.f;
    if (i < 128) g_colsum[i] = 0.f;
    if (i < 16384)       g_wb[i] = __float2bfloat16(Wg[i]);
    else if (i < 65536)  g_wb[i] = __float2bfloat16(Wc1[i - 16384]);
    else if (i < 114688) g_wb[i] = __float2bfloat16(Wc2[i - 65536]);
}

// ---------------- degree histogram (2 edges/thread) -------------------------
__global__ void count_deg_kernel(const int* __restrict__ dst, int e) {
    int i = blockIdx.x * blockDim.x + threadIdx.x;
    int half = e >> 1;
    if (i < half) {
        int2 d = ((const int2*)dst)[i];
        atomicAdd(&g_deg[d.x], 1);
        atomicAdd(&g_deg[d.y], 1);
    }
    if (i == 0 && (e & 1)) atomicAdd(&g_deg[dst[e - 1]], 1);
}

// ---------------- scan phase A ----------------------------------------------
__global__ void scanA_kernel(int n) {
    __shared__ int sm[1024];
    int t = threadIdx.x;
    int i = blockIdx.x * 1024 + t;
    int v = (i < n) ? g_deg[i] : 0;
    if (i < n) g_norm[i] = rsqrtf((float)(v > 0 ? v : 1));
    sm[t] = v;
    __syncthreads();
    #pragma unroll
    for (int off = 1; off < 1024; off <<= 1) {
        int x = sm[t];
        if (t >= off) x += sm[t - off];
        __syncthreads();
        sm[t] = x;
        __syncthreads();
    }
    if (i < n) g_rowptr[i] = sm[t] - v;
    if (t == 1023) g_blocksum[blockIdx.x] = sm[t];
}

// ---------------- scan phase C ----------------------------------------------
__global__ void scanC_kernel(int n, int e, int nb) {
    __shared__ int pref[64];
    int t = threadIdx.x;
    if (t < 64) {
        int s = 0;
        for (int j = 0; j < t && j < nb; j++) s += g_blocksum[j];
        pref[t] = s;
    }
    __syncthreads();
    int i = blockIdx.x * blockDim.x + t;
    if (i < n) {
        int r = g_rowptr[i] + pref[i >> 10];
        g_rowptr[i] = r;
        g_cursor[i] = r;
    }
    if (i == 0) g_rowptr[n] = e;
}

// ---------------- CSR scatter: fused edge records {src*16, norm(src)} ------
__global__ void scatter_kernel(const int* __restrict__ src,
                               const int* __restrict__ dst, int e) {
    int i = blockIdx.x * blockDim.x + threadIdx.x;
    int half = e >> 1;
    if (i < half) {
        int2 d = ((const int2*)dst)[i];
        int2 s = ((const int2*)src)[i];
        int p0 = atomicAdd(&g_cursor[d.x], 1);
        g_csredge[p0] = make_uint2((unsigned)(s.x * 16),
                                   __float_as_uint(g_norm[s.x]));
        int p1 = atomicAdd(&g_cursor[d.y], 1);
        g_csredge[p1] = make_uint2((unsigned)(s.y * 16),
                                   __float_as_uint(g_norm[s.y]));
    }
    if (i == 0 && (e & 1)) {
        int s = src[e - 1];
        int p = atomicAdd(&g_cursor[dst[e - 1]], 1);
        g_csredge[p] = make_uint2((unsigned)(s * 16),
                                  __float_as_uint(g_norm[s]));
    }
}

// ---------------- half-warp-per-node SpMM (uint4 rows, fused edges) ---------
// hout[v] = norm[v] * sum_{s in CSR[v]} norm[s] * hin[s]
__global__ __launch_bounds__(256)
void spmm_kernel(const uint4* __restrict__ hin,
                 uint4* __restrict__ hout, int n) {
    int hw   = threadIdx.x >> 4;          // half-warp slot 0..15
    int node = blockIdx.x * 16 + hw;
    int lane = threadIdx.x & 15;
    if (node >= n) return;
    int beg = g_rowptr[node], end = g_rowptr[node + 1];
    const uint4* hp = hin + lane;         // pre-biased by lane
    float a0 = 0.f, a1 = 0.f, a2 = 0.f, a3 = 0.f;
    float a4 = 0.f, a5 = 0.f, a6 = 0.f, a7 = 0.f;
    #pragma unroll 4
    for (int e = beg; e < end; e++) {
        uint2 em = __ldg(&g_csredge[e]);   // broadcast LDG.64
        uint4 p  = __ldg(&hp[em.x]);       // LDG.128 feature row slice
        float w  = __uint_as_float(em.y);
        float2 f0 = __bfloat1622float2(*(__nv_bfloat162*)&p.x);
        float2 f1 = __bfloat1622float2(*(__nv_bfloat162*)&p.y);
        float2 f2 = __bfloat1622float2(*(__nv_bfloat162*)&p.z);
        float2 f3 = __bfloat1622float2(*(__nv_bfloat162*)&p.w);
        a0 = fmaf(f0.x, w, a0);  a1 = fmaf(f0.y, w, a1);
        a2 = fmaf(f1.x, w, a2);  a3 = fmaf(f1.y, w, a3);
        a4 = fmaf(f2.x, w, a4);  a5 = fmaf(f2.y, w, a5);
        a6 = fmaf(f3.x, w, a6);  a7 = fmaf(f3.y, w, a7);
    }
    float nv = g_norm[node];
    __nv_bfloat162 o0 = __float22bfloat162_rn(make_float2(a0 * nv, a1 * nv));
    __nv_bfloat162 o1 = __float22bfloat162_rn(make_float2(a2 * nv, a3 * nv));
    __nv_bfloat162 o2 = __float22bfloat162_rn(make_float2(a4 * nv, a5 * nv));
    __nv_bfloat162 o3 = __float22bfloat162_rn(make_float2(a6 * nv, a7 * nv));
    hout[node * 16 + lane] = make_uint4(*(unsigned*)&o0, *(unsigned*)&o1,
                                        *(unsigned*)&o2, *(unsigned*)&o3);
}

// ---------------- tensor-core GEMM helpers ----------------------------------
__device__ __forceinline__ void ldsm4(unsigned (&r)[4], unsigned addr) {
    asm volatile("ldmatrix.sync.aligned.m8n8.x4.shared.b16 {%0,%1,%2,%3}, [%4];"
        : "=r"(r[0]), "=r"(r[1]), "=r"(r[2]), "=r"(r[3]) : "r"(addr));
}
__device__ __forceinline__ void ldsm4t(unsigned (&r)[4], unsigned addr) {
    asm volatile("ldmatrix.sync.aligned.m8n8.x4.trans.shared.b16 {%0,%1,%2,%3}, [%4];"
        : "=r"(r[0]), "=r"(r[1]), "=r"(r[2]), "=r"(r[3]) : "r"(addr));
}
__device__ __forceinline__ void mma_bf16(float (&c)[4], const unsigned (&a)[4],
                                         unsigned b0, unsigned b1) {
    asm volatile("mma.sync.aligned.m16n8k16.row.col.f32.bf16.bf16.f32 "
        "{%0,%1,%2,%3}, {%4,%5,%6,%7}, {%8,%9}, {%0,%1,%2,%3};"
        : "+f"(c[0]), "+f"(c[1]), "+f"(c[2]), "+f"(c[3])
        : "r"(a[0]), "r"(a[1]), "r"(a[2]), "r"(a[3]), "r"(b0), "r"(b1));
}

// C = act([A|...] @ Wb) -> bf16x2 packed output.
// Af non-null: A is fp32 (gating path), converted during smem load.
// statacc non-null: fused BN stats (per-col sum / sumsq of pre-rounding fp32).
#define A_STRIDE 56
#define B_STRIDE 136
__global__ __launch_bounds__(256, 2)
void gemm_bf16_kernel(const __nv_bfloat16* __restrict__ A0,
                      const __nv_bfloat16* __restrict__ A1,
                      const __nv_bfloat16* __restrict__ A2,
                      const float* __restrict__ Af,
                      const __nv_bfloat16* __restrict__ Wb,
                      const float* __restrict__ bias,
                      unsigned int* __restrict__ outb,
                      float* __restrict__ statacc,
                      int nrows, int ktiles, int act) {
    __shared__ __align__(16) unsigned short As[128 * A_STRIDE];
    __shared__ __align__(16) unsigned short Bs[32 * B_STRIDE];
    __shared__ float smstat[256];

    int tid  = threadIdx.x;
    int lane = tid & 31;
    int wid  = tid >> 5;
    int m_warp = (wid >> 1) * 32;
    int n_warp = (wid & 1) * 64;
    int r0 = blockIdx.x * 128;

    unsigned as_base = (unsigned)__cvta_generic_to_shared(As);
    unsigned bs_base = (unsigned)__cvta_generic_to_shared(Bs);

    float acc[2][8][4];
    #pragma unroll
    for (int mt = 0; mt < 2; mt++)
        #pragma unroll
        for (int nt = 0; nt < 8; nt++)
            #pragma unroll
            for (int k = 0; k < 4; k++) acc[mt][nt][k] = 0.f;

    for (int kt = 0; kt < ktiles; kt++) {
        int seg = kt >> 2;
        const __nv_bfloat16* Ap = (seg == 0) ? A0 : ((seg == 1) ? A1 : A2);
        int kk = (kt & 3) * 32;

        // A tile [128 x 32] bf16 (convert from fp32 if Af path)
        #pragma unroll
        for (int it = 0; it < 2; it++) {
            int idx = tid + it * 256;
            int row = idx >> 2;
            int ch  = idx & 3;
            int gr  = r0 + row;
            uint4 v = make_uint4(0u, 0u, 0u, 0u);
            if (Af) {
                if (gr < nrows) {
                    float4 u0 = *(const float4*)(Af + gr * 128 + kk + ch * 8);
                    float4 u1 = *(const float4*)(Af + gr * 128 + kk + ch * 8 + 4);
                    __nv_bfloat162 p0 = __float22bfloat162_rn(make_float2(u0.x, u0.y));
                    __nv_bfloat162 p1 = __float22bfloat162_rn(make_float2(u0.z, u0.w));
                    __nv_bfloat162 p2 = __float22bfloat162_rn(make_float2(u1.x, u1.y));
                    __nv_bfloat162 p3 = __float22bfloat162_rn(make_float2(u1.z, u1.w));
                    v = make_uint4(*(unsigned*)&p0, *(unsigned*)&p1,
                                   *(unsigned*)&p2, *(unsigned*)&p3);
                }
            } else if (gr < nrows) {
                v = *(const uint4*)(Ap + gr * 128 + kk + ch * 8);
            }
            *(uint4*)(As + row * A_STRIDE + ch * 8) = v;
        }
        // B tile [32 x 128] bf16
        #pragma unroll
        for (int it = 0; it < 2; it++) {
            int idx = tid + it * 256;
            int row = idx >> 4;
            int ch  = idx & 15;
            uint4 v = *(const uint4*)(Wb + (kt * 32 + row) * 128 + ch * 8);
            *(uint4*)(Bs + row * B_STRIDE + ch * 8) = v;
        }
        __syncthreads();

        #pragma unroll
        for (int ksub = 0; ksub < 2; ksub++) {
            unsigned a[2][4];
            #pragma unroll
            for (int mt = 0; mt < 2; mt++) {
                unsigned addr = as_base +
                    ((m_warp + mt * 16 + (lane & 15)) * A_STRIDE +
                     ksub * 16 + (lane >> 4) * 8) * 2;
                ldsm4(a[mt], addr);
            }
            unsigned b[4][4];
            #pragma unroll
            for (int nt2 = 0; nt2 < 4; nt2++) {
                unsigned addr = bs_base +
                    ((ksub * 16 + (lane & 15)) * B_STRIDE +
                     n_warp + nt2 * 16 + (lane >> 4) * 8) * 2;
                ldsm4t(b[nt2], addr);
            }
            #pragma unroll
            for (int mt = 0; mt < 2; mt++)
                #pragma unroll
                for (int nt = 0; nt < 8; nt++)
                    mma_bf16(acc[mt][nt], a[mt],
                             b[nt >> 1][(nt & 1) * 2],
                             b[nt >> 1][(nt & 1) * 2 + 1]);
        }
        __syncthreads();
    }

    // ---------------- epilogue -------------------------------------------
    int g  = lane >> 2;
    int t4 = lane & 3;
    if (statacc) {
        smstat[tid] = 0.f;
        __syncthreads();
    }
    #pragma unroll
    for (int mt = 0; mt < 2; mt++) {
        int row0 = r0 + m_warp + mt * 16 + g;
        bool v0 = row0 < nrows;
        bool v1 = row0 + 8 < nrows;
        #pragma unroll
        for (int nt = 0; nt < 8; nt++) {
            int col = n_warp + nt * 8 + 2 * t4;
            float c0 = acc[mt][nt][0], c1 = acc[mt][nt][1];
            float c2 = acc[mt][nt][2], c3 = acc[mt][nt][3];
            if (act) {
                float b0 = bias[col], b1 = bias[col + 1];
                c0 = 1.f / (1.f + __expf(-(c0 + b0)));
                c1 = 1.f / (1.f + __expf(-(c1 + b1)));
                c2 = 1.f / (1.f + __expf(-(c2 + b0)));
                c3 = 1.f / (1.f + __expf(-(c3 + b1)));
            }
            if (statacc) {
                float a0 = v0 ? c0 : 0.f, a1 = v0 ? c1 : 0.f;
                float a2 = v1 ? c2 : 0.f, a3 = v1 ? c3 : 0.f;
                float s0 = a0 + a2, s1 = a1 + a3;
                float q0 = a0 * a0 + a2 * a2, q1 = a1 * a1 + a3 * a3;
                #pragma unroll
                for (int m = 4; m < 32; m <<= 1) {
                    s0 += __shfl_xor_sync(0xffffffffu, s0, m);
                    s1 += __shfl_xor_sync(0xffffffffu, s1, m);
                    q0 += __shfl_xor_sync(0xffffffffu, q0, m);
                    q1 += __shfl_xor_sync(0xffffffffu, q1, m);
                }
                if (g == 0) {
                    atomicAdd(&smstat[col], s0);
                    atomicAdd(&smstat[col + 1], s1);
                    atomicAdd(&smstat[128 + col], q0);
                    atomicAdd(&smstat[128 + col + 1], q1);
                }
            }
            if (v0) {
                __nv_bfloat162 p = __float22bfloat162_rn(make_float2(c0, c1));
                outb[row0 * 64 + (col >> 1)] = *(unsigned*)&p;
            }
            if (v1) {
                __nv_bfloat162 p = __float22bfloat162_rn(make_float2(c2, c3));
                outb[(row0 + 8) * 64 + (col >> 1)] = *(unsigned*)&p;
            }
        }
    }
    if (statacc) {
        __syncthreads();
        atomicAdd(&statacc[tid], smstat[tid]);
    }
}

// ---------------- BN apply + ReLU (bf16 z in, optional bf16 out, colsum) ----
__global__ void bn_apply_kernel(const unsigned int* __restrict__ z2,
                                unsigned int* __restrict__ hout2,
                                const float* __restrict__ acc,
                                const float* __restrict__ gamma,
                                const float* __restrict__ beta,
                                int n, int docol) {
    int cp  = threadIdx.x & 63;
    int sub = threadIdx.x >> 6;
    int c0 = cp * 2, c1 = c0 + 1;
    float inv_n = 1.f / (float)n;
    float mu0 = acc[c0] * inv_n, mu1 = acc[c1] * inv_n;
    float va0 = acc[128 + c0] * inv_n - mu0 * mu0;
    float va1 = acc[128 + c1] * inv_n - mu1 * mu1;
    float s0 = rsqrtf(va0 + BN_EPS) * gamma[c0];
    float s1 = rsqrtf(va1 + BN_EPS) * gamma[c1];
    float h0 = beta[c0] - mu0 * s0;
    float h1 = beta[c1] - mu1 * s1;
    int r0 = blockIdx.x * 512;
    int r1 = min(r0 + 512, n);
    float cs0 = 0.f, cs1 = 0.f;
    for (int r = r0 + sub; r < r1; r += 4) {
        unsigned p = z2[r * 64 + cp];
        float2 f = __bfloat1622float2(*(__nv_bfloat162*)&p);
        float v0 = fmaxf(fmaf(f.x, s0, h0), 0.f);
        float v1 = fmaxf(fmaf(f.y, s1, h1), 0.f);
        if (hout2) {
            __nv_bfloat162 o = __float22bfloat162_rn(make_float2(v0, v1));
            hout2[r * 64 + cp] = *(unsigned*)&o;
        }
        cs0 += v0;
        cs1 += v1;
    }
    if (docol) {
        atomicAdd(&g_colsum[c0], cs0);
        atomicAdd(&g_colsum[c1], cs1);
    }
}

// ---------------- readout: out = colmean(h) @ Wd + bd -----------------------
__global__ void final_kernel(const float* __restrict__ Wd,
                             const float* __restrict__ bd,
                             float* __restrict__ out, int n) {
    int j = threadIdx.x;
    float inv_n = 1.f / (float)n;
    float acc = bd[j];
    #pragma unroll 4
    for (int c = 0; c < D; c++)
        acc = fmaf(__ldg(&g_colsum[c]) * inv_n, Wd[c * 256 + j], acc);
    out[j] = acc;
}

// ---------------- launch ----------------------------------------------------
extern "C" void kernel_launch(void* const* d_in, const int* in_sizes, int n_in,
                              void* d_out, int out_size) {
    const float* features = (const float*)d_in[0];
    const int*   src      = (const int*)  d_in[1];
    const int*   dst      = (const int*)  d_in[2];
    const float* Wg  = (const float*)d_in[3];
    const float* bg  = (const float*)d_in[4];
    const float* Wc1 = (const float*)d_in[5];
    const float* g1  = (const float*)d_in[6];
    const float* b1  = (const float*)d_in[7];
    const float* Wc2 = (const float*)d_in[8];
    const float* g2  = (const float*)d_in[9];
    const float* b2  = (const float*)d_in[10];
    const float* Wd  = (const float*)d_in[11];
    const float* bd  = (const float*)d_in[12];
    float* out = (float*)d_out;

    int N = in_sizes[0] / D;
    int E = in_sizes[1];

    void* p;
    __nv_bfloat16 *hb0, *hb1, *hb2, *wb;
    unsigned int* zb;
    float* bnacc;
    cudaGetSymbolAddress(&p, g_hb0);   hb0 = (__nv_bfloat16*)p;
    cudaGetSymbolAddress(&p, g_hb1);   hb1 = (__nv_bfloat16*)p;
    cudaGetSymbolAddress(&p, g_hb2);   hb2 = (__nv_bfloat16*)p;
    cudaGetSymbolAddress(&p, g_wb);    wb  = (__nv_bfloat16*)p;
    cudaGetSymbolAddress(&p, g_zb);    zb  = (unsigned int*)p;
    cudaGetSymbolAddress(&p, g_bnacc); bnacc = (float*)p;

    int gb  = (N + 127) / 128;
    int bnb = (N + 511) / 512;
    int spb = (N + 15) / 16;
    int nsb = (N + 1023) / 1024;
    int eb2 = ((E >> 1) + 255) / 256;

    // fork/join: run the graph-structure chain concurrently with the gating
    // GEMM. Streams/events are created+destroyed per call (no device mem).
    cudaStream_t s1;
    cudaStreamCreateWithFlags(&s1, cudaStreamNonBlocking);
    cudaEvent_t e0, e1;
    cudaEventCreateWithFlags(&e0, cudaEventDisableTiming);
    cudaEventCreateWithFlags(&e1, cudaEventDisableTiming);

    // init on main stream (weights for GEMM + zeroed deg for setup chain)
    init_kernel<<<448, 256>>>(N, Wg, Wc1, Wc2);
    cudaEventRecord(e0, 0);
    cudaStreamWaitEvent(s1, e0, 0);

    // setup chain on side stream
    count_deg_kernel<<<eb2, 256, 0, s1>>>(dst, E);
    scanA_kernel<<<nsb, 1024, 0, s1>>>(N);
    scanC_kernel<<<(N + 255) / 256, 256, 0, s1>>>(N, E, nsb);
    scatter_kernel<<<eb2, 256, 0, s1>>>(src, dst, E);
    cudaEventRecord(e1, s1);

    // gating GEMM on main stream, concurrent with setup chain
    gemm_bf16_kernel<<<gb, 256>>>(nullptr, nullptr, nullptr, features, wb, bg,
                                  (unsigned int*)hb0, nullptr, N, 4, 1);

    // join: spmm needs both the gating output and the CSR structure
    cudaStreamWaitEvent(0, e1, 0);

    // ---- layer 1 ----
    spmm_kernel<<<spb, 256>>>((const uint4*)hb0, (uint4*)hb1, N);
    spmm_kernel<<<spb, 256>>>((const uint4*)hb1, (uint4*)hb2, N);
    gemm_bf16_kernel<<<gb, 256>>>(hb0, hb1, hb2, nullptr, wb + 16384, nullptr,
                                  zb, bnacc, N, 12, 0);
    bn_apply_kernel<<<bnb, 256>>>(zb, (unsigned int*)hb0, bnacc, g1, b1, N, 0);

    // ---- layer 2 ----
    spmm_kernel<<<spb, 256>>>((const uint4*)hb0, (uint4*)hb1, N);
    spmm_kernel<<<spb, 256>>>((const uint4*)hb1, (uint4*)hb2, N);
    gemm_bf16_kernel<<<gb, 256>>>(hb0, hb1, hb2, nullptr, wb + 65536, nullptr,
                                  zb, bnacc + 256, N, 12, 0);
    bn_apply_kernel<<<bnb, 256>>>(zb, nullptr, bnacc + 256, g2, b2, N, 1);

    // readout
    final_kernel<<<1, 256>>>(Wd, bd, out, N);

    cudaEventDestroy(e0);
    cudaEventDestroy(e1);
    cudaStreamDestroy(s1);
}